// round 2
// baseline (speedup 1.0000x reference)
#include <cuda_runtime.h>
#include <cstdint>
#include <math.h>

#define NN 50000      // nodes
#define EE 800000     // raw edges
#define ET 850000     // edges + self loops
#define FH 128        // F_IN == NHID
#define NH 4          // heads
#define NC 64         // classes
#define SLOPE 0.2f

// ---------------- static device scratch (no runtime alloc allowed) ----------
static __device__ float g_xs[(size_t)NH * NN * FH];   // layer1 transformed feats
static __device__ float g_x[(size_t)NN * NH * FH];    // layer1 output / layer2 input
static __device__ float g_xs2[(size_t)NN * NC];       // layer2 transformed feats
static __device__ float g_ssrc[NH * NN];
static __device__ float g_sdst[NH * NN];
static __device__ float g_den[NH * NN];
static __device__ float g_ex[(size_t)NH * ET];
static __device__ float g_ssrc2[NN];
static __device__ float g_sdst2[NN];
static __device__ float g_den2[NN];
static __device__ float g_ex2[ET];

__device__ __forceinline__ float lrelu(float x) { return x > 0.f ? x : SLOPE * x; }

__device__ __forceinline__ void red_add_v4(float* addr, float4 v) {
    asm volatile("red.global.add.v4.f32 [%0], {%1,%2,%3,%4};"
                 :: "l"(addr), "f"(v.x), "f"(v.y), "f"(v.z), "f"(v.w)
                 : "memory");
}

// ---------------- zero-init accumulators -----------------------------------
__global__ void init_kernel(float* __restrict__ out) {
    const long stride = (long)gridDim.x * blockDim.x;
    const long t = (long)blockIdx.x * blockDim.x + threadIdx.x;
    const float4 z = make_float4(0.f, 0.f, 0.f, 0.f);
    float4* px = reinterpret_cast<float4*>(g_x);
    for (long i = t; i < (long)NN * NH * FH / 4; i += stride) px[i] = z;
    float4* pd = reinterpret_cast<float4*>(g_den);
    for (long i = t; i < (long)NH * NN / 4; i += stride) pd[i] = z;
    float4* pd2 = reinterpret_cast<float4*>(g_den2);
    for (long i = t; i < (long)NN / 4; i += stride) pd2[i] = z;
    float4* po = reinterpret_cast<float4*>(out);
    for (long i = t; i < (long)NN * NC / 4; i += stride) po[i] = z;
}

// ---------------- register-blocked fp32 GEMM: C[M,N] = A[M,K] @ B[K,N] ------
template<int BM, int BN, int BK, int TM, int TN>
__global__ void sgemm_kernel(const float* __restrict__ A, const float* __restrict__ B,
                             float* __restrict__ C, int M, int N, int K,
                             size_t sA, size_t sB, size_t sC) {
    constexpr int THREADS = (BM / TM) * (BN / TN);
    __shared__ __align__(16) float As[BK][BM];
    __shared__ __align__(16) float Bs[BK][BN];
    const int tid = threadIdx.x;
    A += (size_t)blockIdx.z * sA;
    B += (size_t)blockIdx.z * sB;
    C += (size_t)blockIdx.z * sC;
    const int rowBase = blockIdx.x * BM;
    const int colBase = blockIdx.y * BN;
    const int tx = tid % (BN / TN);
    const int ty = tid / (BN / TN);
    float acc[TM][TN] = {};

    for (int k0 = 0; k0 < K; k0 += BK) {
        for (int i = tid; i < BM * BK / 4; i += THREADS) {
            int r = i / (BK / 4);
            int c = (i % (BK / 4)) * 4;
            float4 v = make_float4(0.f, 0.f, 0.f, 0.f);
            if (rowBase + r < M)
                v = *reinterpret_cast<const float4*>(&A[(size_t)(rowBase + r) * K + k0 + c]);
            As[c + 0][r] = v.x; As[c + 1][r] = v.y; As[c + 2][r] = v.z; As[c + 3][r] = v.w;
        }
        for (int i = tid; i < BK * BN / 4; i += THREADS) {
            int r = i / (BN / 4);
            int c = (i % (BN / 4)) * 4;
            *reinterpret_cast<float4*>(&Bs[r][c]) =
                *reinterpret_cast<const float4*>(&B[(size_t)(k0 + r) * N + colBase + c]);
        }
        __syncthreads();
        #pragma unroll
        for (int k = 0; k < BK; k++) {
            float ra[TM], rb[TN];
            #pragma unroll
            for (int i = 0; i < TM; i += 4)
                *reinterpret_cast<float4*>(&ra[i]) = *reinterpret_cast<const float4*>(&As[k][ty * TM + i]);
            #pragma unroll
            for (int j = 0; j < TN; j += 4)
                *reinterpret_cast<float4*>(&rb[j]) = *reinterpret_cast<const float4*>(&Bs[k][tx * TN + j]);
            #pragma unroll
            for (int i = 0; i < TM; i++)
                #pragma unroll
                for (int j = 0; j < TN; j++)
                    acc[i][j] += ra[i] * rb[j];
        }
        __syncthreads();
    }
    #pragma unroll
    for (int i = 0; i < TM; i++) {
        int row = rowBase + ty * TM + i;
        if (row < M) {
            #pragma unroll
            for (int j = 0; j < TN; j += 4)
                *reinterpret_cast<float4*>(&C[(size_t)row * N + colBase + tx * TN + j]) =
                    *reinterpret_cast<float4*>(&acc[i][j]);
        }
    }
}

// ---------------- per-node attention logits (layer 1) -----------------------
__global__ void dots1_kernel(const float* __restrict__ att_src, const float* __restrict__ att_dst) {
    int w = (int)(((long)blockIdx.x * blockDim.x + threadIdx.x) >> 5);
    int lane = threadIdx.x & 31;
    if (w >= NN * NH) return;
    int h = w & 3, n = w >> 2;
    const float4 v = *reinterpret_cast<const float4*>(&g_xs[((size_t)h * NN + n) * FH + lane * 4]);
    const float4 a = *reinterpret_cast<const float4*>(&att_src[h * FH + lane * 4]);
    const float4 b = *reinterpret_cast<const float4*>(&att_dst[h * FH + lane * 4]);
    float ds = v.x * a.x + v.y * a.y + v.z * a.z + v.w * a.w;
    float dd = v.x * b.x + v.y * b.y + v.z * b.z + v.w * b.w;
    #pragma unroll
    for (int o = 16; o > 0; o >>= 1) {
        ds += __shfl_down_sync(0xffffffffu, ds, o);
        dd += __shfl_down_sync(0xffffffffu, dd, o);
    }
    if (lane == 0) { g_ssrc[h * NN + n] = ds; g_sdst[h * NN + n] = dd; }
}

// ---------------- edge pass A (layer 1): exp + denom ------------------------
__global__ void edgea1_kernel(const int* __restrict__ edge) {
    int e = blockIdx.x * blockDim.x + threadIdx.x;
    if (e >= ET) return;
    int s, d;
    if (e < EE) { s = edge[e]; d = edge[EE + e]; } else { s = d = e - EE; }
    #pragma unroll
    for (int h = 0; h < NH; h++) {
        float v = lrelu(g_ssrc[h * NN + s] + g_sdst[h * NN + d]);
        float ex = expf(v);
        g_ex[(size_t)h * ET + e] = ex;
        atomicAdd(&g_den[h * NN + d], ex);
    }
}

// ---------------- edge pass B (layer 1): weighted scatter -------------------
__global__ void edgeb1_kernel(const int* __restrict__ edge) {
    long gt = (long)blockIdx.x * blockDim.x + threadIdx.x;
    long w = gt >> 5;
    int lane = threadIdx.x & 31;
    if (w >= (long)ET * NH) return;
    int h = (int)(w & 3);
    int e = (int)(w >> 2);
    int s, d;
    if (e < EE) { s = edge[e]; d = edge[EE + e]; } else { s = d = e - EE; }
    float alpha = g_ex[(size_t)h * ET + e] / g_den[h * NN + d];
    const float4 v = *reinterpret_cast<const float4*>(&g_xs[((size_t)h * NN + s) * FH + lane * 4]);
    red_add_v4(&g_x[(size_t)d * (NH * FH) + h * FH + lane * 4],
               make_float4(alpha * v.x, alpha * v.y, alpha * v.z, alpha * v.w));
}

// ---------------- layer 1 epilogue: + bias, LeakyReLU -----------------------
__global__ void ep1_kernel(const float* __restrict__ bias) {
    const long n4 = (long)NN * NH * FH / 4;
    const long stride = (long)gridDim.x * blockDim.x;
    float4* px = reinterpret_cast<float4*>(g_x);
    for (long i = (long)blockIdx.x * blockDim.x + threadIdx.x; i < n4; i += stride) {
        int col4 = (int)(i & (NH * FH / 4 - 1)) * 4;
        float4 v = px[i];
        const float4 b = *reinterpret_cast<const float4*>(&bias[col4]);
        v.x = lrelu(v.x + b.x); v.y = lrelu(v.y + b.y);
        v.z = lrelu(v.z + b.z); v.w = lrelu(v.w + b.w);
        px[i] = v;
    }
}

// ---------------- per-node attention logits (layer 2) -----------------------
__global__ void dots2_kernel(const float* __restrict__ att_src, const float* __restrict__ att_dst) {
    int w = (int)(((long)blockIdx.x * blockDim.x + threadIdx.x) >> 5);
    int lane = threadIdx.x & 31;
    if (w >= NN) return;
    const float2 v = *reinterpret_cast<const float2*>(&g_xs2[(size_t)w * NC + lane * 2]);
    const float2 a = *reinterpret_cast<const float2*>(&att_src[lane * 2]);
    const float2 b = *reinterpret_cast<const float2*>(&att_dst[lane * 2]);
    float ds = v.x * a.x + v.y * a.y;
    float dd = v.x * b.x + v.y * b.y;
    #pragma unroll
    for (int o = 16; o > 0; o >>= 1) {
        ds += __shfl_down_sync(0xffffffffu, ds, o);
        dd += __shfl_down_sync(0xffffffffu, dd, o);
    }
    if (lane == 0) { g_ssrc2[w] = ds; g_sdst2[w] = dd; }
}

// ---------------- edge pass A (layer 2) ------------------------------------
__global__ void edgea2_kernel(const int* __restrict__ edge) {
    int e = blockIdx.x * blockDim.x + threadIdx.x;
    if (e >= ET) return;
    int s, d;
    if (e < EE) { s = edge[e]; d = edge[EE + e]; } else { s = d = e - EE; }
    float v = lrelu(g_ssrc2[s] + g_sdst2[d]);
    float ex = expf(v);
    g_ex2[e] = ex;
    atomicAdd(&g_den2[d], ex);
}

// ---------------- edge pass B (layer 2) ------------------------------------
__global__ void edgeb2_kernel(const int* __restrict__ edge, float* __restrict__ out) {
    long gt = (long)blockIdx.x * blockDim.x + threadIdx.x;
    long w = gt >> 5;
    int lane = threadIdx.x & 31;
    if (w >= ET) return;
    int e = (int)w;
    int s, d;
    if (e < EE) { s = edge[e]; d = edge[EE + e]; } else { s = d = e - EE; }
    if (lane < 16) {
        float alpha = g_ex2[e] / g_den2[d];
        const float4 v = *reinterpret_cast<const float4*>(&g_xs2[(size_t)s * NC + lane * 4]);
        red_add_v4(&out[(size_t)d * NC + lane * 4],
                   make_float4(alpha * v.x, alpha * v.y, alpha * v.z, alpha * v.w));
    }
}

// ---------------- layer 2 epilogue: + bias, LeakyReLU, tanh -----------------
__global__ void ep2_kernel(float* __restrict__ out, const float* __restrict__ bias_out) {
    const long n4 = (long)NN * NC / 4;
    const long stride = (long)gridDim.x * blockDim.x;
    float4* po = reinterpret_cast<float4*>(out);
    for (long i = (long)blockIdx.x * blockDim.x + threadIdx.x; i < n4; i += stride) {
        int col4 = (int)(i & (NC / 4 - 1)) * 4;
        float4 v = po[i];
        const float4 b = *reinterpret_cast<const float4*>(&bias_out[col4]);
        v.x = tanhf(lrelu(v.x + b.x)); v.y = tanhf(lrelu(v.y + b.y));
        v.z = tanhf(lrelu(v.z + b.z)); v.w = tanhf(lrelu(v.w + b.w));
        po[i] = v;
    }
}

// ---------------- launch ----------------------------------------------------
extern "C" void kernel_launch(void* const* d_in, const int* in_sizes, int n_in,
                              void* d_out, int out_size) {
    const float* type_emb  = (const float*)d_in[0];  // [4,50000,128]
    const int*   edge      = (const int*)d_in[1];    // [2,800000]
    const float* W         = (const float*)d_in[2];  // [4,128,128]
    const float* att_src   = (const float*)d_in[3];  // [4,128]
    const float* att_dst   = (const float*)d_in[4];  // [4,128]
    const float* bias      = (const float*)d_in[5];  // [4,128]
    const float* W_out     = (const float*)d_in[6];  // [512,64]
    const float* att_src_o = (const float*)d_in[7];  // [64]
    const float* att_dst_o = (const float*)d_in[8];  // [64]
    const float* bias_o    = (const float*)d_in[9];  // [64]
    float* out = (float*)d_out;                      // [50000,64]
    (void)in_sizes; (void)n_in; (void)out_size;

    float *p_xs, *p_x, *p_xs2;
    cudaGetSymbolAddress((void**)&p_xs, g_xs);
    cudaGetSymbolAddress((void**)&p_x, g_x);
    cudaGetSymbolAddress((void**)&p_xs2, g_xs2);

    init_kernel<<<1024, 256>>>(out);

    // Layer 1 GEMM: xs[h] = type_emb[h] @ W[h]
    dim3 g1((NN + 127) / 128, 1, NH);
    sgemm_kernel<128, 128, 8, 8, 8><<<g1, 256>>>(type_emb, W, p_xs, NN, FH, FH,
                                                 (size_t)NN * FH, (size_t)FH * FH,
                                                 (size_t)NN * FH);
    dots1_kernel<<<(NN * NH * 32 + 255) / 256, 256>>>(att_src, att_dst);
    edgea1_kernel<<<(ET + 255) / 256, 256>>>(edge);
    edgeb1_kernel<<<(int)(((long)ET * NH * 32 + 255) / 256), 256>>>(edge);
    ep1_kernel<<<4096, 256>>>(bias);

    // Layer 2 GEMM: xs2 = x @ W_out
    dim3 g2((NN + 127) / 128, 1, 1);
    sgemm_kernel<128, 64, 8, 8, 8><<<g2, 128>>>(p_x, W_out, p_xs2, NN, NC, NH * FH,
                                                0, 0, 0);
    dots2_kernel<<<(NN * 32 + 255) / 256, 256>>>(att_src_o, att_dst_o);
    edgea2_kernel<<<(ET + 255) / 256, 256>>>(edge);
    edgeb2_kernel<<<(int)(((long)ET * 32 + 255) / 256), 256>>>(edge, out);
    ep2_kernel<<<2048, 256>>>(out, bias_o);
}

// round 3
// speedup vs baseline: 1.0007x; 1.0007x over previous
#include <cuda_runtime.h>
#include <cstdint>
#include <math.h>

#define NN 50000      // nodes
#define EE 800000     // raw edges
#define ET 850000     // edges + self loops
#define FH 128        // F_IN == NHID
#define NH 4          // heads
#define NC 64         // classes
#define SLOPE 0.2f

// ---------------- static device scratch (no runtime alloc allowed) ----------
static __device__ float g_xs[(size_t)NH * NN * FH];   // layer1 transformed feats
static __device__ float g_x[(size_t)NN * NH * FH];    // layer1 output / layer2 input
static __device__ float g_xs2[(size_t)NN * NC];       // layer2 transformed feats
static __device__ float g_ssrc[NH * NN];
static __device__ float g_sdst[NH * NN];
static __device__ float g_den[NH * NN];
static __device__ float g_ex[(size_t)NH * ET];
static __device__ float g_ssrc2[NN];
static __device__ float g_sdst2[NN];
static __device__ float g_den2[NN];
static __device__ float g_ex2[ET];

__device__ __forceinline__ float lrelu(float x) { return x > 0.f ? x : SLOPE * x; }

__device__ __forceinline__ void red_add_v4(float* addr, float4 v) {
    asm volatile("red.global.add.v4.f32 [%0], {%1,%2,%3,%4};"
                 :: "l"(addr), "f"(v.x), "f"(v.y), "f"(v.z), "f"(v.w)
                 : "memory");
}

// ---------------- zero-init accumulators -----------------------------------
__global__ void init_kernel(float* __restrict__ out) {
    const long stride = (long)gridDim.x * blockDim.x;
    const long t = (long)blockIdx.x * blockDim.x + threadIdx.x;
    const float4 z = make_float4(0.f, 0.f, 0.f, 0.f);
    float4* px = reinterpret_cast<float4*>(g_x);
    for (long i = t; i < (long)NN * NH * FH / 4; i += stride) px[i] = z;
    float4* pd = reinterpret_cast<float4*>(g_den);
    for (long i = t; i < (long)NH * NN / 4; i += stride) pd[i] = z;
    float4* pd2 = reinterpret_cast<float4*>(g_den2);
    for (long i = t; i < (long)NN / 4; i += stride) pd2[i] = z;
    float4* po = reinterpret_cast<float4*>(out);
    for (long i = t; i < (long)NN * NC / 4; i += stride) po[i] = z;
}

// ---------------- register-blocked fp32 GEMM: C[M,N] = A[M,K] @ B[K,N] ------
template<int BM, int BN, int BK, int TM, int TN>
__global__ void sgemm_kernel(const float* __restrict__ A, const float* __restrict__ B,
                             float* __restrict__ C, int M, int N, int K,
                             size_t sA, size_t sB, size_t sC) {
    constexpr int THREADS = (BM / TM) * (BN / TN);
    __shared__ __align__(16) float As[BK][BM];
    __shared__ __align__(16) float Bs[BK][BN];
    const int tid = threadIdx.x;
    A += (size_t)blockIdx.z * sA;
    B += (size_t)blockIdx.z * sB;
    C += (size_t)blockIdx.z * sC;
    const int rowBase = blockIdx.x * BM;
    const int colBase = blockIdx.y * BN;
    const int tx = tid % (BN / TN);
    const int ty = tid / (BN / TN);
    float acc[TM][TN] = {};

    for (int k0 = 0; k0 < K; k0 += BK) {
        for (int i = tid; i < BM * BK / 4; i += THREADS) {
            int r = i / (BK / 4);
            int c = (i % (BK / 4)) * 4;
            float4 v = make_float4(0.f, 0.f, 0.f, 0.f);
            if (rowBase + r < M)
                v = *reinterpret_cast<const float4*>(&A[(size_t)(rowBase + r) * K + k0 + c]);
            As[c + 0][r] = v.x; As[c + 1][r] = v.y; As[c + 2][r] = v.z; As[c + 3][r] = v.w;
        }
        for (int i = tid; i < BK * BN / 4; i += THREADS) {
            int r = i / (BN / 4);
            int c = (i % (BN / 4)) * 4;
            *reinterpret_cast<float4*>(&Bs[r][c]) =
                *reinterpret_cast<const float4*>(&B[(size_t)(k0 + r) * N + colBase + c]);
        }
        __syncthreads();
        #pragma unroll
        for (int k = 0; k < BK; k++) {
            float ra[TM], rb[TN];
            #pragma unroll
            for (int i = 0; i < TM; i += 4)
                *reinterpret_cast<float4*>(&ra[i]) = *reinterpret_cast<const float4*>(&As[k][ty * TM + i]);
            #pragma unroll
            for (int j = 0; j < TN; j += 4)
                *reinterpret_cast<float4*>(&rb[j]) = *reinterpret_cast<const float4*>(&Bs[k][tx * TN + j]);
            #pragma unroll
            for (int i = 0; i < TM; i++)
                #pragma unroll
                for (int j = 0; j < TN; j++)
                    acc[i][j] += ra[i] * rb[j];
        }
        __syncthreads();
    }
    #pragma unroll
    for (int i = 0; i < TM; i++) {
        int row = rowBase + ty * TM + i;
        if (row < M) {
            #pragma unroll
            for (int j = 0; j < TN; j += 4)
                *reinterpret_cast<float4*>(&C[(size_t)row * N + colBase + tx * TN + j]) =
                    *reinterpret_cast<float4*>(&acc[i][j]);
        }
    }
}

// ---------------- per-node attention logits (layer 1) -----------------------
__global__ void dots1_kernel(const float* __restrict__ att_src, const float* __restrict__ att_dst) {
    int w = (int)(((long)blockIdx.x * blockDim.x + threadIdx.x) >> 5);
    int lane = threadIdx.x & 31;
    if (w >= NN * NH) return;
    int h = w & 3, n = w >> 2;
    const float4 v = *reinterpret_cast<const float4*>(&g_xs[((size_t)h * NN + n) * FH + lane * 4]);
    const float4 a = *reinterpret_cast<const float4*>(&att_src[h * FH + lane * 4]);
    const float4 b = *reinterpret_cast<const float4*>(&att_dst[h * FH + lane * 4]);
    float ds = v.x * a.x + v.y * a.y + v.z * a.z + v.w * a.w;
    float dd = v.x * b.x + v.y * b.y + v.z * b.z + v.w * b.w;
    #pragma unroll
    for (int o = 16; o > 0; o >>= 1) {
        ds += __shfl_down_sync(0xffffffffu, ds, o);
        dd += __shfl_down_sync(0xffffffffu, dd, o);
    }
    if (lane == 0) { g_ssrc[h * NN + n] = ds; g_sdst[h * NN + n] = dd; }
}

// ---------------- edge pass A (layer 1): exp + denom ------------------------
__global__ void edgea1_kernel(const int* __restrict__ edge) {
    int e = blockIdx.x * blockDim.x + threadIdx.x;
    if (e >= ET) return;
    int s, d;
    if (e < EE) { s = edge[e]; d = edge[EE + e]; } else { s = d = e - EE; }
    #pragma unroll
    for (int h = 0; h < NH; h++) {
        float v = lrelu(g_ssrc[h * NN + s] + g_sdst[h * NN + d]);
        float ex = expf(v);
        g_ex[(size_t)h * ET + e] = ex;
        atomicAdd(&g_den[h * NN + d], ex);
    }
}

// ---------------- edge pass B (layer 1): weighted scatter -------------------
__global__ void edgeb1_kernel(const int* __restrict__ edge) {
    long gt = (long)blockIdx.x * blockDim.x + threadIdx.x;
    long w = gt >> 5;
    int lane = threadIdx.x & 31;
    if (w >= (long)ET * NH) return;
    int h = (int)(w & 3);
    int e = (int)(w >> 2);
    int s, d;
    if (e < EE) { s = edge[e]; d = edge[EE + e]; } else { s = d = e - EE; }
    float alpha = g_ex[(size_t)h * ET + e] / g_den[h * NN + d];
    const float4 v = *reinterpret_cast<const float4*>(&g_xs[((size_t)h * NN + s) * FH + lane * 4]);
    red_add_v4(&g_x[(size_t)d * (NH * FH) + h * FH + lane * 4],
               make_float4(alpha * v.x, alpha * v.y, alpha * v.z, alpha * v.w));
}

// ---------------- layer 1 epilogue: + bias, LeakyReLU -----------------------
__global__ void ep1_kernel(const float* __restrict__ bias) {
    const long n4 = (long)NN * NH * FH / 4;
    const long stride = (long)gridDim.x * blockDim.x;
    float4* px = reinterpret_cast<float4*>(g_x);
    for (long i = (long)blockIdx.x * blockDim.x + threadIdx.x; i < n4; i += stride) {
        int col4 = (int)(i & (NH * FH / 4 - 1)) * 4;
        float4 v = px[i];
        const float4 b = *reinterpret_cast<const float4*>(&bias[col4]);
        v.x = lrelu(v.x + b.x); v.y = lrelu(v.y + b.y);
        v.z = lrelu(v.z + b.z); v.w = lrelu(v.w + b.w);
        px[i] = v;
    }
}

// ---------------- per-node attention logits (layer 2) -----------------------
__global__ void dots2_kernel(const float* __restrict__ att_src, const float* __restrict__ att_dst) {
    int w = (int)(((long)blockIdx.x * blockDim.x + threadIdx.x) >> 5);
    int lane = threadIdx.x & 31;
    if (w >= NN) return;
    const float2 v = *reinterpret_cast<const float2*>(&g_xs2[(size_t)w * NC + lane * 2]);
    const float2 a = *reinterpret_cast<const float2*>(&att_src[lane * 2]);
    const float2 b = *reinterpret_cast<const float2*>(&att_dst[lane * 2]);
    float ds = v.x * a.x + v.y * a.y;
    float dd = v.x * b.x + v.y * b.y;
    #pragma unroll
    for (int o = 16; o > 0; o >>= 1) {
        ds += __shfl_down_sync(0xffffffffu, ds, o);
        dd += __shfl_down_sync(0xffffffffu, dd, o);
    }
    if (lane == 0) { g_ssrc2[w] = ds; g_sdst2[w] = dd; }
}

// ---------------- edge pass A (layer 2) ------------------------------------
__global__ void edgea2_kernel(const int* __restrict__ edge) {
    int e = blockIdx.x * blockDim.x + threadIdx.x;
    if (e >= ET) return;
    int s, d;
    if (e < EE) { s = edge[e]; d = edge[EE + e]; } else { s = d = e - EE; }
    float v = lrelu(g_ssrc2[s] + g_sdst2[d]);
    float ex = expf(v);
    g_ex2[e] = ex;
    atomicAdd(&g_den2[d], ex);
}

// ---------------- edge pass B (layer 2) ------------------------------------
__global__ void edgeb2_kernel(const int* __restrict__ edge, float* __restrict__ out) {
    long gt = (long)blockIdx.x * blockDim.x + threadIdx.x;
    long w = gt >> 5;
    int lane = threadIdx.x & 31;
    if (w >= ET) return;
    int e = (int)w;
    int s, d;
    if (e < EE) { s = edge[e]; d = edge[EE + e]; } else { s = d = e - EE; }
    if (lane < 16) {
        float alpha = g_ex2[e] / g_den2[d];
        const float4 v = *reinterpret_cast<const float4*>(&g_xs2[(size_t)s * NC + lane * 4]);
        red_add_v4(&out[(size_t)d * NC + lane * 4],
                   make_float4(alpha * v.x, alpha * v.y, alpha * v.z, alpha * v.w));
    }
}

// ---------------- layer 2 epilogue: + bias, LeakyReLU, tanh -----------------
__global__ void ep2_kernel(float* __restrict__ out, const float* __restrict__ bias_out) {
    const long n4 = (long)NN * NC / 4;
    const long stride = (long)gridDim.x * blockDim.x;
    float4* po = reinterpret_cast<float4*>(out);
    for (long i = (long)blockIdx.x * blockDim.x + threadIdx.x; i < n4; i += stride) {
        int col4 = (int)(i & (NC / 4 - 1)) * 4;
        float4 v = po[i];
        const float4 b = *reinterpret_cast<const float4*>(&bias_out[col4]);
        v.x = tanhf(lrelu(v.x + b.x)); v.y = tanhf(lrelu(v.y + b.y));
        v.z = tanhf(lrelu(v.z + b.z)); v.w = tanhf(lrelu(v.w + b.w));
        po[i] = v;
    }
}

// ---------------- launch ----------------------------------------------------
extern "C" void kernel_launch(void* const* d_in, const int* in_sizes, int n_in,
                              void* d_out, int out_size) {
    const float* type_emb  = (const float*)d_in[0];  // [4,50000,128]
    const int*   edge      = (const int*)d_in[1];    // [2,800000]
    const float* W         = (const float*)d_in[2];  // [4,128,128]
    const float* att_src   = (const float*)d_in[3];  // [4,128]
    const float* att_dst   = (const float*)d_in[4];  // [4,128]
    const float* bias      = (const float*)d_in[5];  // [4,128]
    const float* W_out     = (const float*)d_in[6];  // [512,64]
    const float* att_src_o = (const float*)d_in[7];  // [64]
    const float* att_dst_o = (const float*)d_in[8];  // [64]
    const float* bias_o    = (const float*)d_in[9];  // [64]
    float* out = (float*)d_out;                      // [50000,64]
    (void)in_sizes; (void)n_in; (void)out_size;

    float *p_xs, *p_x, *p_xs2;
    cudaGetSymbolAddress((void**)&p_xs, g_xs);
    cudaGetSymbolAddress((void**)&p_x, g_x);
    cudaGetSymbolAddress((void**)&p_xs2, g_xs2);

    init_kernel<<<1024, 256>>>(out);

    // Layer 1 GEMM: xs[h] = type_emb[h] @ W[h]
    dim3 g1((NN + 127) / 128, 1, NH);
    sgemm_kernel<128, 128, 8, 8, 8><<<g1, 256>>>(type_emb, W, p_xs, NN, FH, FH,
                                                 (size_t)NN * FH, (size_t)FH * FH,
                                                 (size_t)NN * FH);
    dots1_kernel<<<(NN * NH * 32 + 255) / 256, 256>>>(att_src, att_dst);
    edgea1_kernel<<<(ET + 255) / 256, 256>>>(edge);
    edgeb1_kernel<<<(int)(((long)ET * NH * 32 + 255) / 256), 256>>>(edge);
    ep1_kernel<<<4096, 256>>>(bias);

    // Layer 2 GEMM: xs2 = x @ W_out
    dim3 g2((NN + 127) / 128, 1, 1);
    sgemm_kernel<128, 64, 8, 8, 8><<<g2, 128>>>(p_x, W_out, p_xs2, NN, NC, NH * FH,
                                                0, 0, 0);
    dots2_kernel<<<(NN * 32 + 255) / 256, 256>>>(att_src_o, att_dst_o);
    edgea2_kernel<<<(ET + 255) / 256, 256>>>(edge);
    edgeb2_kernel<<<(int)(((long)ET * 32 + 255) / 256), 256>>>(edge, out);
    ep2_kernel<<<2048, 256>>>(out, bias_o);
}

// round 8
// speedup vs baseline: 1.8548x; 1.8534x over previous
#include <cuda_runtime.h>
#include <cstdint>
#include <math.h>

#define NN 50000      // nodes
#define EE 800000     // raw edges
#define ET 850000     // edges + self loops
#define FH 128        // F_IN == NHID
#define NH 4          // heads
#define NC 64         // classes
#define SLOPE 0.2f

// ---------------- static device scratch (no runtime alloc allowed) ----------
static __device__ float g_xs[(size_t)NH * NN * FH];   // layer1 transformed feats
static __device__ float g_x[(size_t)NN * NH * FH];    // layer1 output / layer2 input
static __device__ float g_xs2[(size_t)NN * NC];       // layer2 transformed feats
static __device__ float g_ssrc[NH * NN];
static __device__ float g_sdst[NH * NN];
static __device__ float g_ssrc2[NN];
static __device__ float g_sdst2[NN];
static __device__ int   g_deg[NN];
static __device__ int   g_row[NN + 1];
static __device__ int   g_fill[NN];
static __device__ int   g_csrc[ET];

__device__ __forceinline__ float lrelu(float x) { return x > 0.f ? x : SLOPE * x; }

// ---------------- CSR build --------------------------------------------------
__global__ void zero_deg_kernel() {
    for (int i = blockIdx.x * blockDim.x + threadIdx.x; i < NN;
         i += gridDim.x * blockDim.x)
        g_deg[i] = 0;
}

__global__ void count_kernel(const int* __restrict__ edge) {
    int e = blockIdx.x * blockDim.x + threadIdx.x;
    if (e >= ET) return;
    int d = (e < EE) ? edge[EE + e] : (e - EE);
    atomicAdd(&g_deg[d], 1);
}

#define SCAN_T 1024
__global__ void scan_kernel() {
    __shared__ int sh[SCAN_T];
    const int tid = threadIdx.x;
    const int CH = (NN + SCAN_T - 1) / SCAN_T;
    const int base = tid * CH;
    int sum = 0;
    for (int k = 0; k < CH; k++) {
        int i = base + k;
        if (i < NN) sum += g_deg[i];
    }
    sh[tid] = sum;
    __syncthreads();
    // Hillis-Steele inclusive scan
    for (int off = 1; off < SCAN_T; off <<= 1) {
        int v = (tid >= off) ? sh[tid - off] : 0;
        __syncthreads();
        sh[tid] += v;
        __syncthreads();
    }
    int run = (tid == 0) ? 0 : sh[tid - 1];
    for (int k = 0; k < CH; k++) {
        int i = base + k;
        if (i < NN) {
            g_row[i] = run;
            g_fill[i] = run;
            run += g_deg[i];
        }
    }
    if (tid == SCAN_T - 1) g_row[NN] = run;
}

__global__ void fill_kernel(const int* __restrict__ edge) {
    int e = blockIdx.x * blockDim.x + threadIdx.x;
    if (e >= ET) return;
    int s, d;
    if (e < EE) { s = edge[e]; d = edge[EE + e]; } else { s = d = e - EE; }
    int pos = atomicAdd(&g_fill[d], 1);
    g_csrc[pos] = s;
}

// ---------------- register-blocked fp32 GEMM: C[M,N] = A[M,K] @ B[K,N] ------
template<int BM, int BN, int BK, int TM, int TN>
__global__ void sgemm_kernel(const float* __restrict__ A, const float* __restrict__ B,
                             float* __restrict__ C, int M, int N, int K,
                             size_t sA, size_t sB, size_t sC) {
    constexpr int THREADS = (BM / TM) * (BN / TN);
    __shared__ __align__(16) float As[BK][BM];
    __shared__ __align__(16) float Bs[BK][BN];
    const int tid = threadIdx.x;
    A += (size_t)blockIdx.z * sA;
    B += (size_t)blockIdx.z * sB;
    C += (size_t)blockIdx.z * sC;
    const int rowBase = blockIdx.x * BM;
    const int colBase = blockIdx.y * BN;
    const int tx = tid % (BN / TN);
    const int ty = tid / (BN / TN);
    float acc[TM][TN] = {};

    for (int k0 = 0; k0 < K; k0 += BK) {
        for (int i = tid; i < BM * BK / 4; i += THREADS) {
            int r = i / (BK / 4);
            int c = (i % (BK / 4)) * 4;
            float4 v = make_float4(0.f, 0.f, 0.f, 0.f);
            if (rowBase + r < M)
                v = *reinterpret_cast<const float4*>(&A[(size_t)(rowBase + r) * K + k0 + c]);
            As[c + 0][r] = v.x; As[c + 1][r] = v.y; As[c + 2][r] = v.z; As[c + 3][r] = v.w;
        }
        for (int i = tid; i < BK * BN / 4; i += THREADS) {
            int r = i / (BN / 4);
            int c = (i % (BN / 4)) * 4;
            *reinterpret_cast<float4*>(&Bs[r][c]) =
                *reinterpret_cast<const float4*>(&B[(size_t)(k0 + r) * N + colBase + c]);
        }
        __syncthreads();
        #pragma unroll
        for (int k = 0; k < BK; k++) {
            float ra[TM], rb[TN];
            #pragma unroll
            for (int i = 0; i < TM; i += 4)
                *reinterpret_cast<float4*>(&ra[i]) = *reinterpret_cast<const float4*>(&As[k][ty * TM + i]);
            #pragma unroll
            for (int j = 0; j < TN; j += 4)
                *reinterpret_cast<float4*>(&rb[j]) = *reinterpret_cast<const float4*>(&Bs[k][tx * TN + j]);
            #pragma unroll
            for (int i = 0; i < TM; i++)
                #pragma unroll
                for (int j = 0; j < TN; j++)
                    acc[i][j] += ra[i] * rb[j];
        }
        __syncthreads();
    }
    #pragma unroll
    for (int i = 0; i < TM; i++) {
        int row = rowBase + ty * TM + i;
        if (row < M) {
            #pragma unroll
            for (int j = 0; j < TN; j += 4)
                *reinterpret_cast<float4*>(&C[(size_t)row * N + colBase + tx * TN + j]) =
                    *reinterpret_cast<float4*>(&acc[i][j]);
        }
    }
}

// ---------------- per-node attention logits (layer 1) -----------------------
__global__ void dots1_kernel(const float* __restrict__ att_src, const float* __restrict__ att_dst) {
    int w = (int)(((long)blockIdx.x * blockDim.x + threadIdx.x) >> 5);
    int lane = threadIdx.x & 31;
    if (w >= NN * NH) return;
    int h = w & 3, n = w >> 2;
    const float4 v = *reinterpret_cast<const float4*>(&g_xs[((size_t)h * NN + n) * FH + lane * 4]);
    const float4 a = *reinterpret_cast<const float4*>(&att_src[h * FH + lane * 4]);
    const float4 b = *reinterpret_cast<const float4*>(&att_dst[h * FH + lane * 4]);
    float ds = v.x * a.x + v.y * a.y + v.z * a.z + v.w * a.w;
    float dd = v.x * b.x + v.y * b.y + v.z * b.z + v.w * b.w;
    #pragma unroll
    for (int o = 16; o > 0; o >>= 1) {
        ds += __shfl_down_sync(0xffffffffu, ds, o);
        dd += __shfl_down_sync(0xffffffffu, dd, o);
    }
    if (lane == 0) { g_ssrc[h * NN + n] = ds; g_sdst[h * NN + n] = dd; }
}

// ---------------- layer 1 fused gather: softmax-agg + bias + lrelu ----------
// one warp per (node, head); single pass accumulates numerator and denominator
__global__ void gather1_kernel(const float* __restrict__ bias) {
    long w = ((long)blockIdx.x * blockDim.x + threadIdx.x) >> 5;
    int lane = threadIdx.x & 31;
    if (w >= (long)NN * NH) return;
    int h = (int)(w & 3);
    int n = (int)(w >> 2);

    const int beg = g_row[n];
    const int end = g_row[n + 1];
    const float sd = g_sdst[h * NN + n];
    const float* __restrict__ xsh = &g_xs[(size_t)h * NN * FH];
    const float* __restrict__ ssh = &g_ssrc[h * NN];

    float4 acc = make_float4(0.f, 0.f, 0.f, 0.f);
    float den = 0.f;

    int s = (beg < end) ? g_csrc[beg] : 0;
    for (int j = beg; j < end; j++) {
        int snext = (j + 1 < end) ? g_csrc[j + 1] : 0;   // prefetch next src
        float e = lrelu(ssh[s] + sd);
        float ex = __expf(e);
        const float4 v = *reinterpret_cast<const float4*>(&xsh[(size_t)s * FH + lane * 4]);
        den += ex;
        acc.x += ex * v.x; acc.y += ex * v.y;
        acc.z += ex * v.z; acc.w += ex * v.w;
        s = snext;
    }
    const float inv = 1.f / den;   // self-loop guarantees den > 0
    const float4 b = *reinterpret_cast<const float4*>(&bias[h * FH + lane * 4]);
    float4 o;
    o.x = lrelu(acc.x * inv + b.x);
    o.y = lrelu(acc.y * inv + b.y);
    o.z = lrelu(acc.z * inv + b.z);
    o.w = lrelu(acc.w * inv + b.w);
    *reinterpret_cast<float4*>(&g_x[(size_t)n * (NH * FH) + h * FH + lane * 4]) = o;
}

// ---------------- per-node attention logits (layer 2) -----------------------
__global__ void dots2_kernel(const float* __restrict__ att_src, const float* __restrict__ att_dst) {
    int w = (int)(((long)blockIdx.x * blockDim.x + threadIdx.x) >> 5);
    int lane = threadIdx.x & 31;
    if (w >= NN) return;
    const float2 v = *reinterpret_cast<const float2*>(&g_xs2[(size_t)w * NC + lane * 2]);
    const float2 a = *reinterpret_cast<const float2*>(&att_src[lane * 2]);
    const float2 b = *reinterpret_cast<const float2*>(&att_dst[lane * 2]);
    float ds = v.x * a.x + v.y * a.y;
    float dd = v.x * b.x + v.y * b.y;
    #pragma unroll
    for (int o = 16; o > 0; o >>= 1) {
        ds += __shfl_down_sync(0xffffffffu, ds, o);
        dd += __shfl_down_sync(0xffffffffu, dd, o);
    }
    if (lane == 0) { g_ssrc2[w] = ds; g_sdst2[w] = dd; }
}

// ---------------- layer 2 fused gather: softmax-agg + bias + lrelu + tanh ---
__global__ void gather2_kernel(float* __restrict__ out, const float* __restrict__ bias_out) {
    long w = ((long)blockIdx.x * blockDim.x + threadIdx.x) >> 5;
    int lane = threadIdx.x & 31;
    if (w >= NN) return;
    int n = (int)w;

    const int beg = g_row[n];
    const int end = g_row[n + 1];
    const float sd = g_sdst2[n];

    float2 acc = make_float2(0.f, 0.f);
    float den = 0.f;

    int s = (beg < end) ? g_csrc[beg] : 0;
    for (int j = beg; j < end; j++) {
        int snext = (j + 1 < end) ? g_csrc[j + 1] : 0;
        float e = lrelu(g_ssrc2[s] + sd);
        float ex = __expf(e);
        const float2 v = *reinterpret_cast<const float2*>(&g_xs2[(size_t)s * NC + lane * 2]);
        den += ex;
        acc.x += ex * v.x; acc.y += ex * v.y;
        s = snext;
    }
    const float inv = 1.f / den;
    const float2 b = *reinterpret_cast<const float2*>(&bias_out[lane * 2]);
    float2 o;
    o.x = tanhf(lrelu(acc.x * inv + b.x));
    o.y = tanhf(lrelu(acc.y * inv + b.y));
    *reinterpret_cast<float2*>(&out[(size_t)n * NC + lane * 2]) = o;
}

// ---------------- launch ----------------------------------------------------
extern "C" void kernel_launch(void* const* d_in, const int* in_sizes, int n_in,
                              void* d_out, int out_size) {
    const float* type_emb  = (const float*)d_in[0];  // [4,50000,128]
    const int*   edge      = (const int*)d_in[1];    // [2,800000]
    const float* W         = (const float*)d_in[2];  // [4,128,128]
    const float* att_src   = (const float*)d_in[3];  // [4,128]
    const float* att_dst   = (const float*)d_in[4];  // [4,128]
    const float* bias      = (const float*)d_in[5];  // [4,128]
    const float* W_out     = (const float*)d_in[6];  // [512,64]
    const float* att_src_o = (const float*)d_in[7];  // [64]
    const float* att_dst_o = (const float*)d_in[8];  // [64]
    const float* bias_o    = (const float*)d_in[9];  // [64]
    float* out = (float*)d_out;                      // [50000,64]
    (void)in_sizes; (void)n_in; (void)out_size;

    float *p_xs, *p_x, *p_xs2;
    cudaGetSymbolAddress((void**)&p_xs, g_xs);
    cudaGetSymbolAddress((void**)&p_x, g_x);
    cudaGetSymbolAddress((void**)&p_xs2, g_xs2);

    // ---- CSR build (dst-sorted adjacency, shared by both layers) ----
    zero_deg_kernel<<<64, 256>>>();
    count_kernel<<<(ET + 255) / 256, 256>>>(edge);
    scan_kernel<<<1, SCAN_T>>>();
    fill_kernel<<<(ET + 255) / 256, 256>>>(edge);

    // ---- Layer 1 ----
    dim3 g1((NN + 127) / 128, 1, NH);
    sgemm_kernel<128, 128, 8, 8, 8><<<g1, 256>>>(type_emb, W, p_xs, NN, FH, FH,
                                                 (size_t)NN * FH, (size_t)FH * FH,
                                                 (size_t)NN * FH);
    dots1_kernel<<<(NN * NH * 32 + 255) / 256, 256>>>(att_src, att_dst);
    gather1_kernel<<<(int)(((long)NN * NH * 32 + 255) / 256), 256>>>(bias);

    // ---- Layer 2 ----
    dim3 g2((NN + 127) / 128, 1, 1);
    sgemm_kernel<128, 64, 8, 8, 8><<<g2, 128>>>(p_x, W_out, p_xs2, NN, NC, NH * FH,
                                                0, 0, 0);
    dots2_kernel<<<(NN * 32 + 255) / 256, 256>>>(att_src_o, att_dst_o);
    gather2_kernel<<<(NN * 32 + 255) / 256, 256>>>(out, bias_o);
}

// round 9
// speedup vs baseline: 2.8737x; 1.5493x over previous
#include <cuda_runtime.h>
#include <cuda_fp16.h>
#include <cstdint>
#include <math.h>

#define NN 50000      // nodes
#define EE 800000     // raw edges
#define ET 850000     // edges + self loops
#define FH 128        // F_IN == NHID
#define NH 4          // heads
#define NC 64         // classes
#define SLOPE 0.2f

// ---------------- static device scratch (no runtime alloc allowed) ----------
static __device__ __half g_xsh[(size_t)NH * NN * FH];  // layer1 feats, fp16
static __device__ float  g_x[(size_t)NN * NH * FH];    // layer1 out / layer2 in (fp32)
static __device__ __half g_xs2h[(size_t)NN * NC];      // layer2 feats, fp16
static __device__ float  g_ssrc[NH * NN];
static __device__ float  g_sdst[NH * NN];
static __device__ float  g_ssrc2[NN];
static __device__ float  g_sdst2[NN];
static __device__ int    g_deg[NN];
static __device__ int    g_row[NN + 1];
static __device__ int    g_fill[NN];
static __device__ int    g_csrc[ET];

__device__ __forceinline__ float lrelu(float x) { return x > 0.f ? x : SLOPE * x; }

__device__ __forceinline__ uint32_t f2tf32(float f) {
    uint32_t u;
    asm("cvt.rna.tf32.f32 %0, %1;" : "=r"(u) : "f"(f));
    return u;
}

__device__ __forceinline__ void mma_tf32(float* d, const uint32_t* a, const uint32_t* b) {
    asm volatile(
        "mma.sync.aligned.m16n8k8.row.col.f32.tf32.tf32.f32 "
        "{%0,%1,%2,%3}, {%4,%5,%6,%7}, {%8,%9}, {%0,%1,%2,%3};"
        : "+f"(d[0]), "+f"(d[1]), "+f"(d[2]), "+f"(d[3])
        : "r"(a[0]), "r"(a[1]), "r"(a[2]), "r"(a[3]), "r"(b[0]), "r"(b[1]));
}

// ---------------- CSR build --------------------------------------------------
__global__ void zero_deg_kernel() {
    for (int i = blockIdx.x * blockDim.x + threadIdx.x; i < NN;
         i += gridDim.x * blockDim.x)
        g_deg[i] = 0;
}

__global__ void count_kernel(const int* __restrict__ edge) {
    int e = blockIdx.x * blockDim.x + threadIdx.x;
    if (e >= ET) return;
    int d = (e < EE) ? edge[EE + e] : (e - EE);
    atomicAdd(&g_deg[d], 1);
}

#define SCAN_T 1024
__global__ void scan_kernel() {
    __shared__ int sh[SCAN_T];
    const int tid = threadIdx.x;
    const int CH = (NN + SCAN_T - 1) / SCAN_T;
    const int base = tid * CH;
    int sum = 0;
    for (int k = 0; k < CH; k++) {
        int i = base + k;
        if (i < NN) sum += g_deg[i];
    }
    sh[tid] = sum;
    __syncthreads();
    for (int off = 1; off < SCAN_T; off <<= 1) {
        int v = (tid >= off) ? sh[tid - off] : 0;
        __syncthreads();
        sh[tid] += v;
        __syncthreads();
    }
    int run = (tid == 0) ? 0 : sh[tid - 1];
    for (int k = 0; k < CH; k++) {
        int i = base + k;
        if (i < NN) {
            g_row[i] = run;
            g_fill[i] = run;
            run += g_deg[i];
        }
    }
    if (tid == SCAN_T - 1) g_row[NN] = run;
}

__global__ void fill_kernel(const int* __restrict__ edge) {
    int e = blockIdx.x * blockDim.x + threadIdx.x;
    if (e >= ET) return;
    int s, d;
    if (e < EE) { s = edge[e]; d = edge[EE + e]; } else { s = d = e - EE; }
    int pos = atomicAdd(&g_fill[d], 1);
    g_csrc[pos] = s;
}

// ---------------- tf32 tensor-core GEMM with fused dots + fp16 epilogue -----
// C[M,BN] = A[M,K] @ B[K,BN]; one block covers a full output row (grid.y == 1).
// Epilogue: writes fp16 features, and per-row dots with att_src/att_dst.
// Layout: BM=128, BK=32, 256 threads = 8 warps as 4(m) x 2(n); warp tile 32 x WN.
template<int BN, int WN>
__global__ void __launch_bounds__(256)
tf32gemm_kernel(const float* __restrict__ A, const float* __restrict__ B,
                __half* __restrict__ Ch,
                float* __restrict__ dsrc, float* __restrict__ ddst,
                const float* __restrict__ atts, const float* __restrict__ attd,
                int M, int K,
                size_t strA, size_t strB, size_t strC, size_t strD, size_t strAtt) {
    constexpr int BM = 128;
    constexpr int BK = 32;
    constexpr int AST = BK + 4;   // As row stride (uint32)
    constexpr int BST = BN + 8;   // Bs row stride (uint32)
    constexpr int MT = 2;         // 16-row m-tiles per warp (WM=32)
    constexpr int NT = WN / 8;    // 8-col n-tiles per warp

    __shared__ uint32_t As[BM * AST];
    __shared__ uint32_t Bs[BK * BST];
    __shared__ float sds[2][BM];
    __shared__ float sdd[2][BM];

    const int tid = threadIdx.x;
    const int lane = tid & 31;
    const int wid = tid >> 5;
    const int wm = wid >> 1;       // 0..3
    const int wn = wid & 1;        // 0..1
    const int r = lane >> 2;       // 0..7
    const int c = lane & 3;        // 0..3
    const int rowBase = blockIdx.x * BM;

    A    += (size_t)blockIdx.z * strA;
    B    += (size_t)blockIdx.z * strB;
    Ch   += (size_t)blockIdx.z * strC;
    dsrc += (size_t)blockIdx.z * strD;
    ddst += (size_t)blockIdx.z * strD;
    atts += (size_t)blockIdx.z * strAtt;
    attd += (size_t)blockIdx.z * strAtt;

    float acc[MT][NT][4] = {};

    for (int k0 = 0; k0 < K; k0 += BK) {
        // A tile: BM x BK fp32 -> tf32, row-major in smem
        #pragma unroll
        for (int i = tid; i < BM * BK / 4; i += 256) {
            int rr = i >> 3;
            int c4 = (i & 7) * 4;
            float4 v = make_float4(0.f, 0.f, 0.f, 0.f);
            if (rowBase + rr < M)
                v = *reinterpret_cast<const float4*>(&A[(size_t)(rowBase + rr) * K + k0 + c4]);
            uint4 t = make_uint4(f2tf32(v.x), f2tf32(v.y), f2tf32(v.z), f2tf32(v.w));
            *reinterpret_cast<uint4*>(&As[rr * AST + c4]) = t;
        }
        // B tile: BK x BN fp32 -> tf32
        #pragma unroll
        for (int i = tid; i < BK * BN / 4; i += 256) {
            int rr = i / (BN / 4);
            int c4 = (i % (BN / 4)) * 4;
            float4 v = *reinterpret_cast<const float4*>(&B[(size_t)(k0 + rr) * BN + c4]);
            uint4 t = make_uint4(f2tf32(v.x), f2tf32(v.y), f2tf32(v.z), f2tf32(v.w));
            *reinterpret_cast<uint4*>(&Bs[rr * BST + c4]) = t;
        }
        __syncthreads();

        #pragma unroll
        for (int kk = 0; kk < BK; kk += 8) {
            uint32_t af[MT][4];
            #pragma unroll
            for (int mt = 0; mt < MT; mt++) {
                int rb = wm * 32 + mt * 16;
                af[mt][0] = As[(rb + r) * AST + kk + c];
                af[mt][1] = As[(rb + r + 8) * AST + kk + c];
                af[mt][2] = As[(rb + r) * AST + kk + c + 4];
                af[mt][3] = As[(rb + r + 8) * AST + kk + c + 4];
            }
            uint32_t bf[NT][2];
            #pragma unroll
            for (int nt = 0; nt < NT; nt++) {
                int cb = wn * WN + nt * 8 + r;
                bf[nt][0] = Bs[(kk + c) * BST + cb];
                bf[nt][1] = Bs[(kk + c + 4) * BST + cb];
            }
            #pragma unroll
            for (int mt = 0; mt < MT; mt++)
                #pragma unroll
                for (int nt = 0; nt < NT; nt++)
                    mma_tf32(acc[mt][nt], af[mt], bf[nt]);
        }
        __syncthreads();
    }

    // ---- epilogue: fp16 store + fused attention dots ----
    float pds[MT][2] = {}, pdd[MT][2] = {};
    #pragma unroll
    for (int mt = 0; mt < MT; mt++) {
        int row0 = rowBase + wm * 32 + mt * 16 + r;
        #pragma unroll
        for (int nt = 0; nt < NT; nt++) {
            int col0 = wn * WN + nt * 8 + 2 * c;
            float as0 = __ldg(&atts[col0]), as1 = __ldg(&atts[col0 + 1]);
            float ad0 = __ldg(&attd[col0]), ad1 = __ldg(&attd[col0 + 1]);
            float* d = acc[mt][nt];
            pds[mt][0] += d[0] * as0 + d[1] * as1;
            pds[mt][1] += d[2] * as0 + d[3] * as1;
            pdd[mt][0] += d[0] * ad0 + d[1] * ad1;
            pdd[mt][1] += d[2] * ad0 + d[3] * ad1;
            if (row0 < M)
                *reinterpret_cast<__half2*>(&Ch[(size_t)row0 * BN + col0]) =
                    __floats2half2_rn(d[0], d[1]);
            if (row0 + 8 < M)
                *reinterpret_cast<__half2*>(&Ch[(size_t)(row0 + 8) * BN + col0]) =
                    __floats2half2_rn(d[2], d[3]);
        }
    }
    // reduce over the 4 lanes (c = lane&3) sharing each row
    #pragma unroll
    for (int mt = 0; mt < MT; mt++) {
        #pragma unroll
        for (int hh = 0; hh < 2; hh++) {
            pds[mt][hh] += __shfl_xor_sync(0xffffffffu, pds[mt][hh], 1);
            pds[mt][hh] += __shfl_xor_sync(0xffffffffu, pds[mt][hh], 2);
            pdd[mt][hh] += __shfl_xor_sync(0xffffffffu, pdd[mt][hh], 1);
            pdd[mt][hh] += __shfl_xor_sync(0xffffffffu, pdd[mt][hh], 2);
        }
    }
    if (c == 0) {
        #pragma unroll
        for (int mt = 0; mt < MT; mt++) {
            int rloc = wm * 32 + mt * 16 + r;
            sds[wn][rloc] = pds[mt][0];
            sdd[wn][rloc] = pdd[mt][0];
            sds[wn][rloc + 8] = pds[mt][1];
            sdd[wn][rloc + 8] = pdd[mt][1];
        }
    }
    __syncthreads();
    if (tid < BM) {
        int row = rowBase + tid;
        if (row < M) {
            dsrc[row] = sds[0][tid] + sds[1][tid];
            ddst[row] = sdd[0][tid] + sdd[1][tid];
        }
    }
}

// ---------------- layer 1 fused gather: softmax-agg + bias + lrelu ----------
// one warp per node; blockIdx.z = head (head-major for L2 locality)
__global__ void gather1_kernel(const float* __restrict__ bias) {
    const int h = blockIdx.z;
    long n = ((long)blockIdx.x * blockDim.x + threadIdx.x) >> 5;
    int lane = threadIdx.x & 31;
    if (n >= NN) return;

    const int beg = g_row[n];
    const int end = g_row[n + 1];
    const float sd = g_sdst[h * NN + (int)n];
    const __half* __restrict__ xsh = &g_xsh[(size_t)h * NN * FH];
    const float* __restrict__ ssh = &g_ssrc[h * NN];

    float4 acc = make_float4(0.f, 0.f, 0.f, 0.f);
    float den = 0.f;

    int s = (beg < end) ? g_csrc[beg] : 0;
    for (int j = beg; j < end; j++) {
        int snext = (j + 1 < end) ? g_csrc[j + 1] : 0;   // prefetch next src
        float e = lrelu(ssh[s] + sd);
        float ex = __expf(e);
        uint2 u = *reinterpret_cast<const uint2*>(&xsh[(size_t)s * FH + lane * 4]);
        float2 f0 = __half22float2(*reinterpret_cast<__half2*>(&u.x));
        float2 f1 = __half22float2(*reinterpret_cast<__half2*>(&u.y));
        den += ex;
        acc.x += ex * f0.x; acc.y += ex * f0.y;
        acc.z += ex * f1.x; acc.w += ex * f1.y;
        s = snext;
    }
    const float inv = 1.f / den;   // self-loop guarantees den > 0
    const float4 b = *reinterpret_cast<const float4*>(&bias[h * FH + lane * 4]);
    float4 o;
    o.x = lrelu(acc.x * inv + b.x);
    o.y = lrelu(acc.y * inv + b.y);
    o.z = lrelu(acc.z * inv + b.z);
    o.w = lrelu(acc.w * inv + b.w);
    *reinterpret_cast<float4*>(&g_x[(size_t)n * (NH * FH) + h * FH + lane * 4]) = o;
}

// ---------------- layer 2 fused gather: softmax-agg + bias + lrelu + tanh ---
__global__ void gather2_kernel(float* __restrict__ out, const float* __restrict__ bias_out) {
    long n = ((long)blockIdx.x * blockDim.x + threadIdx.x) >> 5;
    int lane = threadIdx.x & 31;
    if (n >= NN) return;

    const int beg = g_row[n];
    const int end = g_row[n + 1];
    const float sd = g_sdst2[n];

    float2 acc = make_float2(0.f, 0.f);
    float den = 0.f;

    int s = (beg < end) ? g_csrc[beg] : 0;
    for (int j = beg; j < end; j++) {
        int snext = (j + 1 < end) ? g_csrc[j + 1] : 0;
        float e = lrelu(g_ssrc2[s] + sd);
        float ex = __expf(e);
        __half2 hv = *reinterpret_cast<const __half2*>(&g_xs2h[(size_t)s * NC + lane * 2]);
        float2 v = __half22float2(hv);
        den += ex;
        acc.x += ex * v.x; acc.y += ex * v.y;
        s = snext;
    }
    const float inv = 1.f / den;
    const float2 b = *reinterpret_cast<const float2*>(&bias_out[lane * 2]);
    float2 o;
    o.x = tanhf(lrelu(acc.x * inv + b.x));
    o.y = tanhf(lrelu(acc.y * inv + b.y));
    *reinterpret_cast<float2*>(&out[(size_t)n * NC + lane * 2]) = o;
}

// ---------------- launch ----------------------------------------------------
extern "C" void kernel_launch(void* const* d_in, const int* in_sizes, int n_in,
                              void* d_out, int out_size) {
    const float* type_emb  = (const float*)d_in[0];  // [4,50000,128]
    const int*   edge      = (const int*)d_in[1];    // [2,800000]
    const float* W         = (const float*)d_in[2];  // [4,128,128]
    const float* att_src   = (const float*)d_in[3];  // [4,128]
    const float* att_dst   = (const float*)d_in[4];  // [4,128]
    const float* bias      = (const float*)d_in[5];  // [4,128]
    const float* W_out     = (const float*)d_in[6];  // [512,64]
    const float* att_src_o = (const float*)d_in[7];  // [64]
    const float* att_dst_o = (const float*)d_in[8];  // [64]
    const float* bias_o    = (const float*)d_in[9];  // [64]
    float* out = (float*)d_out;                      // [50000,64]
    (void)in_sizes; (void)n_in; (void)out_size;

    __half *p_xsh, *p_xs2h;
    float *p_x, *p_ssrc, *p_sdst, *p_ssrc2, *p_sdst2;
    cudaGetSymbolAddress((void**)&p_xsh, g_xsh);
    cudaGetSymbolAddress((void**)&p_x, g_x);
    cudaGetSymbolAddress((void**)&p_xs2h, g_xs2h);
    cudaGetSymbolAddress((void**)&p_ssrc, g_ssrc);
    cudaGetSymbolAddress((void**)&p_sdst, g_sdst);
    cudaGetSymbolAddress((void**)&p_ssrc2, g_ssrc2);
    cudaGetSymbolAddress((void**)&p_sdst2, g_sdst2);

    // ---- CSR build (dst-sorted adjacency, shared by both layers) ----
    zero_deg_kernel<<<64, 256>>>();
    count_kernel<<<(ET + 255) / 256, 256>>>(edge);
    scan_kernel<<<1, SCAN_T>>>();
    fill_kernel<<<(ET + 255) / 256, 256>>>(edge);

    // ---- Layer 1: tf32 GEMM (+fused dots, fp16 feats), then gather ----
    dim3 g1((NN + 127) / 128, 1, NH);
    tf32gemm_kernel<128, 64><<<g1, 256>>>(
        type_emb, W, p_xsh, p_ssrc, p_sdst, att_src, att_dst,
        NN, FH,
        (size_t)NN * FH, (size_t)FH * FH, (size_t)NN * FH, (size_t)NN, (size_t)FH);

    dim3 gg1((NN * 32 + 255) / 256, 1, NH);
    gather1_kernel<<<gg1, 256>>>(bias);

    // ---- Layer 2 ----
    dim3 g2((NN + 127) / 128, 1, 1);
    tf32gemm_kernel<64, 32><<<g2, 256>>>(
        p_x, W_out, p_xs2h, p_ssrc2, p_sdst2, att_src_o, att_dst_o,
        NN, NH * FH, 0, 0, 0, 0, 0);

    gather2_kernel<<<(NN * 32 + 255) / 256, 256>>>(out, bias_o);
}

// round 10
// speedup vs baseline: 3.0370x; 1.0568x over previous
#include <cuda_runtime.h>
#include <cuda_fp16.h>
#include <cstdint>
#include <math.h>

#define NN 50000      // nodes
#define EE 800000     // raw edges
#define ET 850000     // edges + self loops
#define FH 128        // F_IN == NHID
#define NH 4          // heads
#define NC 64         // classes
#define SLOPE 0.2f

// ---------------- static device scratch (no runtime alloc allowed) ----------
static __device__ __half g_xsh[(size_t)NH * NN * FH];  // layer1 feats, fp16
static __device__ __half g_xh[(size_t)NN * NH * FH];   // layer1 out / layer2 in, fp16
static __device__ __half g_xs2h[(size_t)NN * NC];      // layer2 feats, fp16
static __device__ float  g_ssrc[NH * NN];
static __device__ float  g_sdst[NH * NN];
static __device__ float  g_ssrc2[NN];
static __device__ float  g_sdst2[NN];
static __device__ int    g_deg[NN];
static __device__ int    g_row[NN + 1];
static __device__ int    g_fill[NN];
static __device__ int    g_csrc[ET];

__device__ __forceinline__ float lrelu(float x) { return x > 0.f ? x : SLOPE * x; }

__device__ __forceinline__ void mma_f16(float* d, const uint32_t* a, const uint32_t* b) {
    asm volatile(
        "mma.sync.aligned.m16n8k16.row.col.f32.f16.f16.f32 "
        "{%0,%1,%2,%3}, {%4,%5,%6,%7}, {%8,%9}, {%0,%1,%2,%3};"
        : "+f"(d[0]), "+f"(d[1]), "+f"(d[2]), "+f"(d[3])
        : "r"(a[0]), "r"(a[1]), "r"(a[2]), "r"(a[3]), "r"(b[0]), "r"(b[1]));
}
__device__ __forceinline__ void ldsm_x4(uint32_t& r0, uint32_t& r1, uint32_t& r2,
                                        uint32_t& r3, uint32_t a) {
    asm volatile("ldmatrix.sync.aligned.m8n8.x4.shared.b16 {%0,%1,%2,%3}, [%4];"
                 : "=r"(r0), "=r"(r1), "=r"(r2), "=r"(r3) : "r"(a));
}
__device__ __forceinline__ void ldsm_x4_t(uint32_t& r0, uint32_t& r1, uint32_t& r2,
                                          uint32_t& r3, uint32_t a) {
    asm volatile("ldmatrix.sync.aligned.m8n8.x4.trans.shared.b16 {%0,%1,%2,%3}, [%4];"
                 : "=r"(r0), "=r"(r1), "=r"(r2), "=r"(r3) : "r"(a));
}
__device__ __forceinline__ uint32_t h2u(__half2 h) {
    return *reinterpret_cast<uint32_t*>(&h);
}

// ---------------- CSR build --------------------------------------------------
__global__ void count_kernel(const int* __restrict__ edge) {
    int e = blockIdx.x * blockDim.x + threadIdx.x;
    if (e >= ET) return;
    int d = (e < EE) ? edge[EE + e] : (e - EE);
    atomicAdd(&g_deg[d], 1);
}

#define SCAN_T 1024
__global__ void scan_kernel() {
    __shared__ int sh[SCAN_T];
    const int tid = threadIdx.x;
    const int CH = (NN + SCAN_T - 1) / SCAN_T;
    const int base = tid * CH;
    int sum = 0;
    for (int k = 0; k < CH; k++) {
        int i = base + k;
        if (i < NN) sum += g_deg[i];
    }
    sh[tid] = sum;
    __syncthreads();
    for (int off = 1; off < SCAN_T; off <<= 1) {
        int v = (tid >= off) ? sh[tid - off] : 0;
        __syncthreads();
        sh[tid] += v;
        __syncthreads();
    }
    int run = (tid == 0) ? 0 : sh[tid - 1];
    for (int k = 0; k < CH; k++) {
        int i = base + k;
        if (i < NN) {
            g_row[i] = run;
            g_fill[i] = run;
            run += g_deg[i];
        }
    }
    if (tid == SCAN_T - 1) g_row[NN] = run;
}

__global__ void fill_kernel(const int* __restrict__ edge) {
    int e = blockIdx.x * blockDim.x + threadIdx.x;
    if (e >= ET) return;
    int s, d;
    if (e < EE) { s = edge[e]; d = edge[EE + e]; } else { s = d = e - EE; }
    int pos = atomicAdd(&g_fill[d], 1);
    g_csrc[pos] = s;
}

// ---------------- fp16 tensor-core GEMM, double-buffered, fused dots --------
// C[M,BN] = A[M,K] @ B[K,BN]; block covers full output width (grid.y == 1).
// A: fp32 (AHALF=false, converted on smem store) or fp16 (AHALF=true).
// Epilogue: fp16 feature store + per-row dot with att_src/att_dst.
// BM=128, BK=32, 256 threads = 8 warps (4m x 2n); warp tile 32 x WN.
template<int BN, int WN, bool AHALF>
__global__ void __launch_bounds__(256)
hgemm_kernel(const void* __restrict__ Ap, const float* __restrict__ B,
             __half* __restrict__ Ch,
             float* __restrict__ dsrc, float* __restrict__ ddst,
             const float* __restrict__ atts, const float* __restrict__ attd,
             int M, int K,
             size_t strA, size_t strB, size_t strC, size_t strD, size_t strAtt) {
    constexpr int BM = 128;
    constexpr int BK = 32;
    constexpr int AST = 40;        // A smem row stride (halves): 80B, conflict-free
    constexpr int BST = BN + 8;    // B smem row stride (halves): +16B phase shift
    constexpr int MT = 2;
    constexpr int NT = WN / 8;
    constexpr int A_LD = AHALF ? (BM * BK / (8 * 256)) : (BM * BK / (4 * 256));
    constexpr int B_LD = BK * BN / (4 * 256);

    __shared__ __align__(16) __half As[2][BM * AST];
    __shared__ __align__(16) __half Bs[2][BK * BST];
    __shared__ float sds[2][BM], sdd[2][BM];

    const int tid = threadIdx.x;
    const int lane = tid & 31;
    const int wid = tid >> 5;
    const int wm = wid >> 1;
    const int wn = wid & 1;
    const int r = lane >> 2;
    const int c = lane & 3;
    const int rowBase = blockIdx.x * BM;

    const float*  A32 = (const float*)Ap + (size_t)blockIdx.z * strA;
    const __half* A16 = (const __half*)Ap + (size_t)blockIdx.z * strA;
    B    += (size_t)blockIdx.z * strB;
    Ch   += (size_t)blockIdx.z * strC;
    dsrc += (size_t)blockIdx.z * strD;
    ddst += (size_t)blockIdx.z * strD;
    atts += (size_t)blockIdx.z * strAtt;
    attd += (size_t)blockIdx.z * strAtt;

    float acc[MT][NT][4] = {};
    float4 aS32[4];
    uint4  aS16[2];
    float4 bS[4];

    auto stage = [&](int k0) {
        if (AHALF) {
            #pragma unroll
            for (int t = 0; t < A_LD; t++) {
                int idx = tid + t * 256;
                int rr = idx >> 2;            // 4 threads/row (BK/8)
                int c8 = (idx & 3) * 8;
                aS16[t] = (rowBase + rr < M)
                    ? *reinterpret_cast<const uint4*>(&A16[(size_t)(rowBase + rr) * K + k0 + c8])
                    : make_uint4(0, 0, 0, 0);
            }
        } else {
            #pragma unroll
            for (int t = 0; t < A_LD; t++) {
                int idx = tid + t * 256;
                int rr = idx >> 3;            // 8 threads/row (BK/4)
                int c4 = (idx & 7) * 4;
                aS32[t] = (rowBase + rr < M)
                    ? *reinterpret_cast<const float4*>(&A32[(size_t)(rowBase + rr) * K + k0 + c4])
                    : make_float4(0.f, 0.f, 0.f, 0.f);
            }
        }
        #pragma unroll
        for (int t = 0; t < B_LD; t++) {
            int idx = tid + t * 256;
            int rr = idx / (BN / 4);
            int c4 = (idx % (BN / 4)) * 4;
            bS[t] = *reinterpret_cast<const float4*>(&B[(size_t)(k0 + rr) * BN + c4]);
        }
    };

    auto commit = [&](int buf) {
        if (AHALF) {
            #pragma unroll
            for (int t = 0; t < A_LD; t++) {
                int idx = tid + t * 256;
                int rr = idx >> 2;
                int c8 = (idx & 3) * 8;
                *reinterpret_cast<uint4*>(&As[buf][rr * AST + c8]) = aS16[t];
            }
        } else {
            #pragma unroll
            for (int t = 0; t < A_LD; t++) {
                int idx = tid + t * 256;
                int rr = idx >> 3;
                int c4 = (idx & 7) * 4;
                uint2 u = make_uint2(h2u(__floats2half2_rn(aS32[t].x, aS32[t].y)),
                                     h2u(__floats2half2_rn(aS32[t].z, aS32[t].w)));
                *reinterpret_cast<uint2*>(&As[buf][rr * AST + c4]) = u;
            }
        }
        #pragma unroll
        for (int t = 0; t < B_LD; t++) {
            int idx = tid + t * 256;
            int rr = idx / (BN / 4);
            int c4 = (idx % (BN / 4)) * 4;
            uint2 u = make_uint2(h2u(__floats2half2_rn(bS[t].x, bS[t].y)),
                                 h2u(__floats2half2_rn(bS[t].z, bS[t].w)));
            *reinterpret_cast<uint2*>(&Bs[buf][rr * BST + c4]) = u;
        }
    };

    auto compute = [&](int buf) {
        const int m = lane >> 3;
        const int i = lane & 7;
        #pragma unroll
        for (int ks = 0; ks < BK / 16; ks++) {
            const int kk = ks * 16;
            uint32_t af[MT][4];
            #pragma unroll
            for (int mt = 0; mt < MT; mt++) {
                int row = wm * 32 + mt * 16 + (m & 1) * 8 + i;
                int col = kk + (m >> 1) * 8;
                uint32_t addr = (uint32_t)__cvta_generic_to_shared(&As[buf][row * AST + col]);
                ldsm_x4(af[mt][0], af[mt][1], af[mt][2], af[mt][3], addr);
            }
            uint32_t bf[NT][2];
            #pragma unroll
            for (int j = 0; j < NT / 2; j++) {
                int krow = kk + (m & 1) * 8 + i;
                int col = wn * WN + j * 16 + (m >> 1) * 8;
                uint32_t addr = (uint32_t)__cvta_generic_to_shared(&Bs[buf][krow * BST + col]);
                ldsm_x4_t(bf[2 * j][0], bf[2 * j][1], bf[2 * j + 1][0], bf[2 * j + 1][1], addr);
            }
            #pragma unroll
            for (int mt = 0; mt < MT; mt++)
                #pragma unroll
                for (int nt = 0; nt < NT; nt++)
                    mma_f16(acc[mt][nt], af[mt], bf[nt]);
        }
    };

    stage(0);
    commit(0);
    __syncthreads();
    int buf = 0;
    for (int k0 = 0; k0 < K; k0 += BK) {
        if (k0 + BK < K) {
            stage(k0 + BK);      // global loads overlap with mma below
            compute(buf);
            commit(buf ^ 1);
            __syncthreads();
            buf ^= 1;
        } else {
            compute(buf);
        }
    }

    // ---- epilogue: fp16 store + fused attention dots ----
    float pds[MT][2] = {}, pdd[MT][2] = {};
    #pragma unroll
    for (int mt = 0; mt < MT; mt++) {
        int row0 = rowBase + wm * 32 + mt * 16 + r;
        #pragma unroll
        for (int nt = 0; nt < NT; nt++) {
            int col0 = wn * WN + nt * 8 + 2 * c;
            float as0 = __ldg(&atts[col0]), as1 = __ldg(&atts[col0 + 1]);
            float ad0 = __ldg(&attd[col0]), ad1 = __ldg(&attd[col0 + 1]);
            float* d = acc[mt][nt];
            pds[mt][0] += d[0] * as0 + d[1] * as1;
            pds[mt][1] += d[2] * as0 + d[3] * as1;
            pdd[mt][0] += d[0] * ad0 + d[1] * ad1;
            pdd[mt][1] += d[2] * ad0 + d[3] * ad1;
            if (row0 < M)
                *reinterpret_cast<__half2*>(&Ch[(size_t)row0 * BN + col0]) =
                    __floats2half2_rn(d[0], d[1]);
            if (row0 + 8 < M)
                *reinterpret_cast<__half2*>(&Ch[(size_t)(row0 + 8) * BN + col0]) =
                    __floats2half2_rn(d[2], d[3]);
        }
    }
    #pragma unroll
    for (int mt = 0; mt < MT; mt++) {
        #pragma unroll
        for (int hh = 0; hh < 2; hh++) {
            pds[mt][hh] += __shfl_xor_sync(0xffffffffu, pds[mt][hh], 1);
            pds[mt][hh] += __shfl_xor_sync(0xffffffffu, pds[mt][hh], 2);
            pdd[mt][hh] += __shfl_xor_sync(0xffffffffu, pdd[mt][hh], 1);
            pdd[mt][hh] += __shfl_xor_sync(0xffffffffu, pdd[mt][hh], 2);
        }
    }
    if (c == 0) {
        #pragma unroll
        for (int mt = 0; mt < MT; mt++) {
            int rloc = wm * 32 + mt * 16 + r;
            sds[wn][rloc] = pds[mt][0];
            sdd[wn][rloc] = pdd[mt][0];
            sds[wn][rloc + 8] = pds[mt][1];
            sdd[wn][rloc + 8] = pdd[mt][1];
        }
    }
    __syncthreads();
    if (tid < BM) {
        int row = rowBase + tid;
        if (row < M) {
            dsrc[row] = sds[0][tid] + sds[1][tid];
            ddst[row] = sdd[0][tid] + sdd[1][tid];
        }
    }
}

// ---------------- layer 1 fused gather: softmax-agg + bias + lrelu ----------
// one warp per node; blockIdx.z = head (head-major for L2 locality)
__global__ void gather1_kernel(const float* __restrict__ bias) {
    const int h = blockIdx.z;
    long n = ((long)blockIdx.x * blockDim.x + threadIdx.x) >> 5;
    int lane = threadIdx.x & 31;
    if (n >= NN) return;

    const int beg = g_row[n];
    const int end = g_row[n + 1];
    const float sd = g_sdst[h * NN + (int)n];
    const __half* __restrict__ xsh = &g_xsh[(size_t)h * NN * FH];
    const float* __restrict__ ssh = &g_ssrc[h * NN];

    float4 acc = make_float4(0.f, 0.f, 0.f, 0.f);
    float den = 0.f;

    int s = (beg < end) ? g_csrc[beg] : 0;
    for (int j = beg; j < end; j++) {
        int snext = (j + 1 < end) ? g_csrc[j + 1] : 0;   // prefetch next src
        float e = lrelu(ssh[s] + sd);
        float ex = __expf(e);
        uint2 u = *reinterpret_cast<const uint2*>(&xsh[(size_t)s * FH + lane * 4]);
        float2 f0 = __half22float2(*reinterpret_cast<__half2*>(&u.x));
        float2 f1 = __half22float2(*reinterpret_cast<__half2*>(&u.y));
        den += ex;
        acc.x += ex * f0.x; acc.y += ex * f0.y;
        acc.z += ex * f1.x; acc.w += ex * f1.y;
        s = snext;
    }
    const float inv = 1.f / den;   // self-loop guarantees den > 0
    const float4 b = *reinterpret_cast<const float4*>(&bias[h * FH + lane * 4]);
    uint2 o;
    o.x = h2u(__floats2half2_rn(lrelu(acc.x * inv + b.x), lrelu(acc.y * inv + b.y)));
    o.y = h2u(__floats2half2_rn(lrelu(acc.z * inv + b.z), lrelu(acc.w * inv + b.w)));
    *reinterpret_cast<uint2*>(&g_xh[(size_t)n * (NH * FH) + h * FH + lane * 4]) = o;
}

// ---------------- layer 2 fused gather: softmax-agg + bias + lrelu + tanh ---
__global__ void gather2_kernel(float* __restrict__ out, const float* __restrict__ bias_out) {
    long n = ((long)blockIdx.x * blockDim.x + threadIdx.x) >> 5;
    int lane = threadIdx.x & 31;
    if (n >= NN) return;

    const int beg = g_row[n];
    const int end = g_row[n + 1];
    const float sd = g_sdst2[n];

    float2 acc = make_float2(0.f, 0.f);
    float den = 0.f;

    int s = (beg < end) ? g_csrc[beg] : 0;
    for (int j = beg; j < end; j++) {
        int snext = (j + 1 < end) ? g_csrc[j + 1] : 0;
        float e = lrelu(g_ssrc2[s] + sd);
        float ex = __expf(e);
        __half2 hv = *reinterpret_cast<const __half2*>(&g_xs2h[(size_t)s * NC + lane * 2]);
        float2 v = __half22float2(hv);
        den += ex;
        acc.x += ex * v.x; acc.y += ex * v.y;
        s = snext;
    }
    const float inv = 1.f / den;
    const float2 b = *reinterpret_cast<const float2*>(&bias_out[lane * 2]);
    float2 o;
    o.x = tanhf(lrelu(acc.x * inv + b.x));
    o.y = tanhf(lrelu(acc.y * inv + b.y));
    *reinterpret_cast<float2*>(&out[(size_t)n * NC + lane * 2]) = o;
}

// ---------------- launch ----------------------------------------------------
extern "C" void kernel_launch(void* const* d_in, const int* in_sizes, int n_in,
                              void* d_out, int out_size) {
    const float* type_emb  = (const float*)d_in[0];  // [4,50000,128]
    const int*   edge      = (const int*)d_in[1];    // [2,800000]
    const float* W         = (const float*)d_in[2];  // [4,128,128]
    const float* att_src   = (const float*)d_in[3];  // [4,128]
    const float* att_dst   = (const float*)d_in[4];  // [4,128]
    const float* bias      = (const float*)d_in[5];  // [4,128]
    const float* W_out     = (const float*)d_in[6];  // [512,64]
    const float* att_src_o = (const float*)d_in[7];  // [64]
    const float* att_dst_o = (const float*)d_in[8];  // [64]
    const float* bias_o    = (const float*)d_in[9];  // [64]
    float* out = (float*)d_out;                      // [50000,64]
    (void)in_sizes; (void)n_in; (void)out_size;

    __half *p_xsh, *p_xh, *p_xs2h;
    float *p_ssrc, *p_sdst, *p_ssrc2, *p_sdst2;
    int *p_deg;
    cudaGetSymbolAddress((void**)&p_xsh, g_xsh);
    cudaGetSymbolAddress((void**)&p_xh, g_xh);
    cudaGetSymbolAddress((void**)&p_xs2h, g_xs2h);
    cudaGetSymbolAddress((void**)&p_ssrc, g_ssrc);
    cudaGetSymbolAddress((void**)&p_sdst, g_sdst);
    cudaGetSymbolAddress((void**)&p_ssrc2, g_ssrc2);
    cudaGetSymbolAddress((void**)&p_sdst2, g_sdst2);
    cudaGetSymbolAddress((void**)&p_deg, g_deg);

    // one-time host objects (created on the uncaptured correctness call)
    static cudaStream_t s_side = nullptr;
    static cudaEvent_t ev_fork = nullptr, ev_join = nullptr;
    if (s_side == nullptr) {
        cudaStreamCreateWithFlags(&s_side, cudaStreamNonBlocking);
        cudaEventCreateWithFlags(&ev_fork, cudaEventDisableTiming);
        cudaEventCreateWithFlags(&ev_join, cudaEventDisableTiming);
    }

    // ---- fork: CSR build on side stream, overlapped with layer-1 GEMM ----
    cudaEventRecord(ev_fork, 0);
    cudaStreamWaitEvent(s_side, ev_fork, 0);
    cudaMemsetAsync(p_deg, 0, NN * sizeof(int), s_side);
    count_kernel<<<(ET + 255) / 256, 256, 0, s_side>>>(edge);
    scan_kernel<<<1, SCAN_T, 0, s_side>>>();
    fill_kernel<<<(ET + 255) / 256, 256, 0, s_side>>>(edge);
    cudaEventRecord(ev_join, s_side);

    // ---- Layer 1 GEMM (fp32 A -> fp16 mma, fused dots) on main stream ----
    dim3 g1((NN + 127) / 128, 1, NH);
    hgemm_kernel<128, 64, false><<<g1, 256>>>(
        type_emb, W, p_xsh, p_ssrc, p_sdst, att_src, att_dst,
        NN, FH,
        (size_t)NN * FH, (size_t)FH * FH, (size_t)NN * FH, (size_t)NN, (size_t)FH);

    // ---- join: gather needs CSR + GEMM ----
    cudaStreamWaitEvent(0, ev_join, 0);

    dim3 gg1((NN * 32 + 255) / 256, 1, NH);
    gather1_kernel<<<gg1, 256>>>(bias);

    // ---- Layer 2: fp16 A GEMM, then gather ----
    dim3 g2((NN + 127) / 128, 1, 1);
    hgemm_kernel<64, 32, true><<<g2, 256>>>(
        p_xh, W_out, p_xs2h, p_ssrc2, p_sdst2, att_src_o, att_dst_o,
        NN, NH * FH, 0, 0, 0, 0, 0);

    gather2_kernel<<<(NN * 32 + 255) / 256, 256>>>(out, bias_o);
}

// round 13
// speedup vs baseline: 3.2722x; 1.0775x over previous
#include <cuda_runtime.h>
#include <cuda_fp16.h>
#include <cstdint>
#include <math.h>

#define NN 50000      // nodes
#define EE 800000     // raw edges
#define ET 850000     // edges + self loops
#define FH 128        // F_IN == NHID
#define NH 4          // heads
#define NC 64         // classes
#define SLOPE 0.2f

// ---------------- static device scratch (no runtime alloc allowed) ----------
static __device__ __half g_xsh[(size_t)NH * NN * FH];  // layer1 feats, fp16
static __device__ __half g_xh[(size_t)NN * NH * FH];   // layer1 out / layer2 in, fp16
static __device__ __half g_xs2h[(size_t)NN * NC];      // layer2 feats, fp16
static __device__ float  g_ssrc[NH * NN];
static __device__ float  g_sdst[NH * NN];
static __device__ float  g_ssrc2[NN];
static __device__ float  g_sdst2[NN];
static __device__ int    g_deg[NN];
static __device__ int    g_row[NN + 1];
static __device__ int    g_fill[NN];
static __device__ int    g_csrc[ET];

__device__ __forceinline__ float lrelu(float x) { return x > 0.f ? x : SLOPE * x; }

__device__ __forceinline__ void mma_f16(float* d, const uint32_t* a, const uint32_t* b) {
    asm volatile(
        "mma.sync.aligned.m16n8k16.row.col.f32.f16.f16.f32 "
        "{%0,%1,%2,%3}, {%4,%5,%6,%7}, {%8,%9}, {%0,%1,%2,%3};"
        : "+f"(d[0]), "+f"(d[1]), "+f"(d[2]), "+f"(d[3])
        : "r"(a[0]), "r"(a[1]), "r"(a[2]), "r"(a[3]), "r"(b[0]), "r"(b[1]));
}
__device__ __forceinline__ void ldsm_x4(uint32_t& r0, uint32_t& r1, uint32_t& r2,
                                        uint32_t& r3, uint32_t a) {
    asm volatile("ldmatrix.sync.aligned.m8n8.x4.shared.b16 {%0,%1,%2,%3}, [%4];"
                 : "=r"(r0), "=r"(r1), "=r"(r2), "=r"(r3) : "r"(a));
}
__device__ __forceinline__ void ldsm_x4_t(uint32_t& r0, uint32_t& r1, uint32_t& r2,
                                          uint32_t& r3, uint32_t a) {
    asm volatile("ldmatrix.sync.aligned.m8n8.x4.trans.shared.b16 {%0,%1,%2,%3}, [%4];"
                 : "=r"(r0), "=r"(r1), "=r"(r2), "=r"(r3) : "r"(a));
}
__device__ __forceinline__ uint32_t h2u(__half2 h) {
    return *reinterpret_cast<uint32_t*>(&h);
}

// ---------------- CSR build --------------------------------------------------
__global__ void count_kernel(const int* __restrict__ edge) {
    int e = blockIdx.x * blockDim.x + threadIdx.x;
    if (e >= ET) return;
    int d = (e < EE) ? edge[EE + e] : (e - EE);
    atomicAdd(&g_deg[d], 1);
}

#define SCAN_T 1024
__global__ void scan_kernel() {
    __shared__ int sh[SCAN_T];
    const int tid = threadIdx.x;
    const int CH = (NN + SCAN_T - 1) / SCAN_T;
    const int base = tid * CH;
    int sum = 0;
    for (int k = 0; k < CH; k++) {
        int i = base + k;
        if (i < NN) sum += g_deg[i];
    }
    sh[tid] = sum;
    __syncthreads();
    for (int off = 1; off < SCAN_T; off <<= 1) {
        int v = (tid >= off) ? sh[tid - off] : 0;
        __syncthreads();
        sh[tid] += v;
        __syncthreads();
    }
    int run = (tid == 0) ? 0 : sh[tid - 1];
    for (int k = 0; k < CH; k++) {
        int i = base + k;
        if (i < NN) {
            g_row[i] = run;
            g_fill[i] = run;
            run += g_deg[i];
        }
    }
    if (tid == SCAN_T - 1) g_row[NN] = run;
}

__global__ void fill_kernel(const int* __restrict__ edge) {
    int e = blockIdx.x * blockDim.x + threadIdx.x;
    if (e >= ET) return;
    int s, d;
    if (e < EE) { s = edge[e]; d = edge[EE + e]; } else { s = d = e - EE; }
    int pos = atomicAdd(&g_fill[d], 1);
    g_csrc[pos] = s;
}

// ---------------- layer-1 GEMM: single-stage full-K (K=128), fused dots -----
// C[h] = A[h] (50000x128, fp32) @ B[h] (128x128, fp32); head = blockIdx.z.
// Whole K fits in smem: one giant load phase (max MLP), one sync, pure mma.
__global__ void __launch_bounds__(256)
hgemm1_kernel(const float* __restrict__ A, const float* __restrict__ B,
              __half* __restrict__ Ch,
              float* __restrict__ dsrc, float* __restrict__ ddst,
              const float* __restrict__ atts, const float* __restrict__ attd) {
    constexpr int BM = 128;
    constexpr int KK = 128;
    constexpr int BN = 128;
    constexpr int AST = 136;   // halves; 272B row stride, ldsm conflict-free
    constexpr int BST = 136;
    constexpr int MT = 2;      // warp tile 32 x 64 (4m x 2n warps)
    constexpr int NT = 8;

    extern __shared__ __align__(16) char dyn[];
    __half* As = reinterpret_cast<__half*>(dyn);            // 34816 B
    __half* Bs = reinterpret_cast<__half*>(dyn + 34816);    // 34816 B
    float* sds = reinterpret_cast<float*>(dyn + 69632);     // 2*128 floats
    float* sdd = reinterpret_cast<float*>(dyn + 70656);     // 2*128 floats

    const int tid = threadIdx.x;
    const int lane = tid & 31;
    const int wid = tid >> 5;
    const int wm = wid >> 1;
    const int wn = wid & 1;
    const int r = lane >> 2;
    const int c = lane & 3;
    const int h = blockIdx.z;
    const int rowBase = blockIdx.x * BM;

    A    += (size_t)h * NN * FH;
    B    += (size_t)h * FH * FH;
    Ch   += (size_t)h * NN * FH;
    dsrc += (size_t)h * NN;
    ddst += (size_t)h * NN;
    atts += h * FH;
    attd += h * FH;

    // ---- load phase: 16+16 independent LDG.128 per thread ----
    #pragma unroll
    for (int t = 0; t < 16; t++) {
        int idx = tid + t * 256;
        int rr = idx >> 5;
        int c4 = (idx & 31) * 4;
        float4 v = make_float4(0.f, 0.f, 0.f, 0.f);
        if (rowBase + rr < NN)
            v = *reinterpret_cast<const float4*>(&A[(size_t)(rowBase + rr) * KK + c4]);
        uint2 u = make_uint2(h2u(__floats2half2_rn(v.x, v.y)),
                             h2u(__floats2half2_rn(v.z, v.w)));
        *reinterpret_cast<uint2*>(&As[rr * AST + c4]) = u;
    }
    #pragma unroll
    for (int t = 0; t < 16; t++) {
        int idx = tid + t * 256;
        int rr = idx >> 5;
        int c4 = (idx & 31) * 4;
        float4 v = *reinterpret_cast<const float4*>(&B[(size_t)rr * BN + c4]);
        uint2 u = make_uint2(h2u(__floats2half2_rn(v.x, v.y)),
                             h2u(__floats2half2_rn(v.z, v.w)));
        *reinterpret_cast<uint2*>(&Bs[rr * BST + c4]) = u;
    }
    __syncthreads();

    // ---- compute phase: 8 k-steps, no further syncs ----
    float acc[MT][NT][4] = {};
    const int m = lane >> 3;
    const int i = lane & 7;
    #pragma unroll
    for (int kk = 0; kk < KK; kk += 16) {
        uint32_t af[MT][4];
        #pragma unroll
        for (int mt = 0; mt < MT; mt++) {
            int row = wm * 32 + mt * 16 + (m & 1) * 8 + i;
            int col = kk + (m >> 1) * 8;
            uint32_t addr = (uint32_t)__cvta_generic_to_shared(&As[row * AST + col]);
            ldsm_x4(af[mt][0], af[mt][1], af[mt][2], af[mt][3], addr);
        }
        uint32_t bf[NT][2];
        #pragma unroll
        for (int j = 0; j < NT / 2; j++) {
            int krow = kk + (m & 1) * 8 + i;
            int col = wn * 64 + j * 16 + (m >> 1) * 8;
            uint32_t addr = (uint32_t)__cvta_generic_to_shared(&Bs[krow * BST + col]);
            ldsm_x4_t(bf[2 * j][0], bf[2 * j][1], bf[2 * j + 1][0], bf[2 * j + 1][1], addr);
        }
        #pragma unroll
        for (int mt = 0; mt < MT; mt++)
            #pragma unroll
            for (int nt = 0; nt < NT; nt++)
                mma_f16(acc[mt][nt], af[mt], bf[nt]);
    }

    // ---- epilogue: fp16 store + fused attention dots ----
    float pds[MT][2] = {}, pdd[MT][2] = {};
    #pragma unroll
    for (int mt = 0; mt < MT; mt++) {
        int row0 = rowBase + wm * 32 + mt * 16 + r;
        #pragma unroll
        for (int nt = 0; nt < NT; nt++) {
            int col0 = wn * 64 + nt * 8 + 2 * c;
            float as0 = __ldg(&atts[col0]), as1 = __ldg(&atts[col0 + 1]);
            float ad0 = __ldg(&attd[col0]), ad1 = __ldg(&attd[col0 + 1]);
            float* d = acc[mt][nt];
            pds[mt][0] += d[0] * as0 + d[1] * as1;
            pds[mt][1] += d[2] * as0 + d[3] * as1;
            pdd[mt][0] += d[0] * ad0 + d[1] * ad1;
            pdd[mt][1] += d[2] * ad0 + d[3] * ad1;
            if (row0 < NN)
                *reinterpret_cast<__half2*>(&Ch[(size_t)row0 * BN + col0]) =
                    __floats2half2_rn(d[0], d[1]);
            if (row0 + 8 < NN)
                *reinterpret_cast<__half2*>(&Ch[(size_t)(row0 + 8) * BN + col0]) =
                    __floats2half2_rn(d[2], d[3]);
        }
    }
    #pragma unroll
    for (int mt = 0; mt < MT; mt++) {
        #pragma unroll
        for (int hh = 0; hh < 2; hh++) {
            pds[mt][hh] += __shfl_xor_sync(0xffffffffu, pds[mt][hh], 1);
            pds[mt][hh] += __shfl_xor_sync(0xffffffffu, pds[mt][hh], 2);
            pdd[mt][hh] += __shfl_xor_sync(0xffffffffu, pdd[mt][hh], 1);
            pdd[mt][hh] += __shfl_xor_sync(0xffffffffu, pdd[mt][hh], 2);
        }
    }
    if (c == 0) {
        #pragma unroll
        for (int mt = 0; mt < MT; mt++) {
            int rloc = wm * 32 + mt * 16 + r;
            sds[wn * 128 + rloc] = pds[mt][0];
            sdd[wn * 128 + rloc] = pdd[mt][0];
            sds[wn * 128 + rloc + 8] = pds[mt][1];
            sdd[wn * 128 + rloc + 8] = pdd[mt][1];
        }
    }
    __syncthreads();
    if (tid < BM) {
        int row = rowBase + tid;
        if (row < NN) {
            dsrc[row] = sds[tid] + sds[128 + tid];
            ddst[row] = sdd[tid] + sdd[128 + tid];
        }
    }
}

// ---------------- layer-2 GEMM: fp16 A, double-buffered, fused dots ---------
// BM=128, BK=32, BN=64; 256 threads = 8 warps (4m x 2n); warp tile 32 x 32.
__global__ void __launch_bounds__(256)
hgemm2_kernel(const __half* __restrict__ A16, const float* __restrict__ B,
              __half* __restrict__ Ch,
              float* __restrict__ dsrc, float* __restrict__ ddst,
              const float* __restrict__ atts, const float* __restrict__ attd,
              int M, int K) {
    constexpr int BM = 128;
    constexpr int BK = 32;
    constexpr int BN = 64;
    constexpr int WN = 32;
    constexpr int AST = 40;
    constexpr int BST = BN + 8;
    constexpr int MT = 2;
    constexpr int NT = WN / 8;
    constexpr int A_LD = BM * BK / (8 * 256);   // 2
    constexpr int B_LD = BK * BN / (4 * 256);   // 2

    __shared__ __align__(16) __half As[2][BM * AST];
    __shared__ __align__(16) __half Bs[2][BK * BST];
    __shared__ float sds[2][BM], sdd[2][BM];

    const int tid = threadIdx.x;
    const int lane = tid & 31;
    const int wid = tid >> 5;
    const int wm = wid >> 1;
    const int wn = wid & 1;
    const int r = lane >> 2;
    const int c = lane & 3;
    const int rowBase = blockIdx.x * BM;

    float acc[MT][NT][4] = {};
    uint4  aS16[A_LD];
    float4 bS[B_LD];

    auto stage = [&](int k0) {
        #pragma unroll
        for (int t = 0; t < A_LD; t++) {
            int idx = tid + t * 256;
            int rr = idx >> 2;
            int c8 = (idx & 3) * 8;
            aS16[t] = (rowBase + rr < M)
                ? *reinterpret_cast<const uint4*>(&A16[(size_t)(rowBase + rr) * K + k0 + c8])
                : make_uint4(0, 0, 0, 0);
        }
        #pragma unroll
        for (int t = 0; t < B_LD; t++) {
            int idx = tid + t * 256;
            int rr = idx / (BN / 4);
            int c4 = (idx % (BN / 4)) * 4;
            bS[t] = *reinterpret_cast<const float4*>(&B[(size_t)(k0 + rr) * BN + c4]);
        }
    };
    auto commit = [&](int buf) {
        #pragma unroll
        for (int t = 0; t < A_LD; t++) {
            int idx = tid + t * 256;
            int rr = idx >> 2;
            int c8 = (idx & 3) * 8;
            *reinterpret_cast<uint4*>(&As[buf][rr * AST + c8]) = aS16[t];
        }
        #pragma unroll
        for (int t = 0; t < B_LD; t++) {
            int idx = tid + t * 256;
            int rr = idx / (BN / 4);
            int c4 = (idx % (BN / 4)) * 4;
            uint2 u = make_uint2(h2u(__floats2half2_rn(bS[t].x, bS[t].y)),
                                 h2u(__floats2half2_rn(bS[t].z, bS[t].w)));
            *reinterpret_cast<uint2*>(&Bs[buf][rr * BST + c4]) = u;
        }
    };
    auto compute = [&](int buf) {
        const int m = lane >> 3;
        const int i = lane & 7;
        #pragma unroll
        for (int ks = 0; ks < BK / 16; ks++) {
            const int kk = ks * 16;
            uint32_t af[MT][4];
            #pragma unroll
            for (int mt = 0; mt < MT; mt++) {
                int row = wm * 32 + mt * 16 + (m & 1) * 8 + i;
                int col = kk + (m >> 1) * 8;
                uint32_t addr = (uint32_t)__cvta_generic_to_shared(&As[buf][row * AST + col]);
                ldsm_x4(af[mt][0], af[mt][1], af[mt][2], af[mt][3], addr);
            }
            uint32_t bf[NT][2];
            #pragma unroll
            for (int j = 0; j < NT / 2; j++) {
                int krow = kk + (m & 1) * 8 + i;
                int col = wn * WN + j * 16 + (m >> 1) * 8;
                uint32_t addr = (uint32_t)__cvta_generic_to_shared(&Bs[buf][krow * BST + col]);
                ldsm_x4_t(bf[2 * j][0], bf[2 * j][1], bf[2 * j + 1][0], bf[2 * j + 1][1], addr);
            }
            #pragma unroll
            for (int mt = 0; mt < MT; mt++)
                #pragma unroll
                for (int nt = 0; nt < NT; nt++)
                    mma_f16(acc[mt][nt], af[mt], bf[nt]);
        }
    };

    stage(0);
    commit(0);
    __syncthreads();
    int buf = 0;
    for (int k0 = 0; k0 < K; k0 += BK) {
        if (k0 + BK < K) {
            stage(k0 + BK);
            compute(buf);
            commit(buf ^ 1);
            __syncthreads();
            buf ^= 1;
        } else {
            compute(buf);
        }
    }

    float pds[MT][2] = {}, pdd[MT][2] = {};
    #pragma unroll
    for (int mt = 0; mt < MT; mt++) {
        int row0 = rowBase + wm * 32 + mt * 16 + r;
        #pragma unroll
        for (int nt = 0; nt < NT; nt++) {
            int col0 = wn * WN + nt * 8 + 2 * c;
            float as0 = __ldg(&atts[col0]), as1 = __ldg(&atts[col0 + 1]);
            float ad0 = __ldg(&attd[col0]), ad1 = __ldg(&attd[col0 + 1]);
            float* d = acc[mt][nt];
            pds[mt][0] += d[0] * as0 + d[1] * as1;
            pds[mt][1] += d[2] * as0 + d[3] * as1;
            pdd[mt][0] += d[0] * ad0 + d[1] * ad1;
            pdd[mt][1] += d[2] * ad0 + d[3] * ad1;
            if (row0 < M)
                *reinterpret_cast<__half2*>(&Ch[(size_t)row0 * BN + col0]) =
                    __floats2half2_rn(d[0], d[1]);
            if (row0 + 8 < M)
                *reinterpret_cast<__half2*>(&Ch[(size_t)(row0 + 8) * BN + col0]) =
                    __floats2half2_rn(d[2], d[3]);
        }
    }
    #pragma unroll
    for (int mt = 0; mt < MT; mt++) {
        #pragma unroll
        for (int hh = 0; hh < 2; hh++) {
            pds[mt][hh] += __shfl_xor_sync(0xffffffffu, pds[mt][hh], 1);
            pds[mt][hh] += __shfl_xor_sync(0xffffffffu, pds[mt][hh], 2);
            pdd[mt][hh] += __shfl_xor_sync(0xffffffffu, pdd[mt][hh], 1);
            pdd[mt][hh] += __shfl_xor_sync(0xffffffffu, pdd[mt][hh], 2);
        }
    }
    if (c == 0) {
        #pragma unroll
        for (int mt = 0; mt < MT; mt++) {
            int rloc = wm * 32 + mt * 16 + r;
            sds[wn][rloc] = pds[mt][0];
            sdd[wn][rloc] = pdd[mt][0];
            sds[wn][rloc + 8] = pds[mt][1];
            sdd[wn][rloc + 8] = pdd[mt][1];
        }
    }
    __syncthreads();
    if (tid < BM) {
        int row = rowBase + tid;
        if (row < M) {
            dsrc[row] = sds[0][tid] + sds[1][tid];
            ddst[row] = sdd[0][tid] + sdd[1][tid];
        }
    }
}

// ---------------- layer 1 fused gather: softmax-agg + bias + lrelu ----------
// one warp per node; blockIdx.z = head; 2-deep software pipeline on all streams
__global__ void gather1_kernel(const float* __restrict__ bias) {
    const int h = blockIdx.z;
    long n = ((long)blockIdx.x * blockDim.x + threadIdx.x) >> 5;
    int lane = threadIdx.x & 31;
    if (n >= NN) return;

    const int beg = g_row[n];
    const int end = g_row[n + 1];
    const float sd = g_sdst[h * NN + (int)n];
    const __half* __restrict__ xsh = &g_xsh[(size_t)h * NN * FH];
    const float* __restrict__ ssh = &g_ssrc[h * NN];

    float4 acc = make_float4(0.f, 0.f, 0.f, 0.f);
    float den = 0.f;

    // prime pipeline (self-loop guarantees beg < end)
    int s = g_csrc[beg];
    float ss = ssh[s];
    uint2 u = *reinterpret_cast<const uint2*>(&xsh[(size_t)s * FH + lane * 4]);

    for (int j = beg; j < end; j++) {
        int sn = (j + 1 < end) ? g_csrc[j + 1] : s;
        float ssn = ssh[sn];                      // next logit (L2, in flight)
        uint2 un = *reinterpret_cast<const uint2*>(&xsh[(size_t)sn * FH + lane * 4]);
        float ex = __expf(lrelu(ss + sd));
        float2 f0 = __half22float2(*reinterpret_cast<__half2*>(&u.x));
        float2 f1 = __half22float2(*reinterpret_cast<__half2*>(&u.y));
        den += ex;
        acc.x += ex * f0.x; acc.y += ex * f0.y;
        acc.z += ex * f1.x; acc.w += ex * f1.y;
        ss = ssn; u = un;
    }
    const float inv = 1.f / den;
    const float4 b = *reinterpret_cast<const float4*>(&bias[h * FH + lane * 4]);
    uint2 o;
    o.x = h2u(__floats2half2_rn(lrelu(acc.x * inv + b.x), lrelu(acc.y * inv + b.y)));
    o.y = h2u(__floats2half2_rn(lrelu(acc.z * inv + b.z), lrelu(acc.w * inv + b.w)));
    *reinterpret_cast<uint2*>(&g_xh[(size_t)n * (NH * FH) + h * FH + lane * 4]) = o;
}

// ---------------- layer 2 fused gather: softmax-agg + bias + lrelu + tanh ---
__global__ void gather2_kernel(float* __restrict__ out, const float* __restrict__ bias_out) {
    long n = ((long)blockIdx.x * blockDim.x + threadIdx.x) >> 5;
    int lane = threadIdx.x & 31;
    if (n >= NN) return;

    const int beg = g_row[n];
    const int end = g_row[n + 1];
    const float sd = g_sdst2[n];

    float2 acc = make_float2(0.f, 0.f);
    float den = 0.f;

    int s = g_csrc[beg];
    float ss = g_ssrc2[s];
    __half2 hv = *reinterpret_cast<const __half2*>(&g_xs2h[(size_t)s * NC + lane * 2]);

    for (int j = beg; j < end; j++) {
        int sn = (j + 1 < end) ? g_csrc[j + 1] : s;
        float ssn = g_ssrc2[sn];
        __half2 hvn = *reinterpret_cast<const __half2*>(&g_xs2h[(size_t)sn * NC + lane * 2]);
        float ex = __expf(lrelu(ss + sd));
        float2 v = __half22float2(hv);
        den += ex;
        acc.x += ex * v.x; acc.y += ex * v.y;
        ss = ssn; hv = hvn;
    }
    const float inv = 1.f / den;
    const float2 b = *reinterpret_cast<const float2*>(&bias_out[lane * 2]);
    float2 o;
    o.x = tanhf(lrelu(acc.x * inv + b.x));
    o.y = tanhf(lrelu(acc.y * inv + b.y));
    *reinterpret_cast<float2*>(&out[(size_t)n * NC + lane * 2]) = o;
}

// ---------------- launch ----------------------------------------------------
extern "C" void kernel_launch(void* const* d_in, const int* in_sizes, int n_in,
                              void* d_out, int out_size) {
    const float* type_emb  = (const float*)d_in[0];  // [4,50000,128]
    const int*   edge      = (const int*)d_in[1];    // [2,800000]
    const float* W         = (const float*)d_in[2];  // [4,128,128]
    const float* att_src   = (const float*)d_in[3];  // [4,128]
    const float* att_dst   = (const float*)d_in[4];  // [4,128]
    const float* bias      = (const float*)d_in[5];  // [4,128]
    const float* W_out     = (const float*)d_in[6];  // [512,64]
    const float* att_src_o = (const float*)d_in[7];  // [64]
    const float* att_dst_o = (const float*)d_in[8];  // [64]
    const float* bias_o    = (const float*)d_in[9];  // [64]
    float* out = (float*)d_out;                      // [50000,64]
    (void)in_sizes; (void)n_in; (void)out_size;

    __half *p_xsh, *p_xh, *p_xs2h;
    float *p_ssrc, *p_sdst, *p_ssrc2, *p_sdst2;
    int *p_deg;
    cudaGetSymbolAddress((void**)&p_xsh, g_xsh);
    cudaGetSymbolAddress((void**)&p_xh, g_xh);
    cudaGetSymbolAddress((void**)&p_xs2h, g_xs2h);
    cudaGetSymbolAddress((void**)&p_ssrc, g_ssrc);
    cudaGetSymbolAddress((void**)&p_sdst, g_sdst);
    cudaGetSymbolAddress((void**)&p_ssrc2, g_ssrc2);
    cudaGetSymbolAddress((void**)&p_sdst2, g_sdst2);
    cudaGetSymbolAddress((void**)&p_deg, g_deg);

    constexpr int GEMM1_SMEM = 71680;   // 2*34816 + 2*1024

    // one-time host objects (created on the uncaptured correctness call)
    static cudaStream_t s_side = nullptr;
    static cudaEvent_t ev_fork = nullptr, ev_join = nullptr;
    if (s_side == nullptr) {
        cudaStreamCreateWithFlags(&s_side, cudaStreamNonBlocking);
        cudaEventCreateWithFlags(&ev_fork, cudaEventDisableTiming);
        cudaEventCreateWithFlags(&ev_join, cudaEventDisableTiming);
        cudaFuncSetAttribute(hgemm1_kernel,
                             cudaFuncAttributeMaxDynamicSharedMemorySize, GEMM1_SMEM);
    }

    // ---- fork: CSR build on side stream, overlapped with layer-1 GEMM ----
    cudaEventRecord(ev_fork, 0);
    cudaStreamWaitEvent(s_side, ev_fork, 0);
    cudaMemsetAsync(p_deg, 0, NN * sizeof(int), s_side);
    count_kernel<<<(ET + 255) / 256, 256, 0, s_side>>>(edge);
    scan_kernel<<<1, SCAN_T, 0, s_side>>>();
    fill_kernel<<<(ET + 255) / 256, 256, 0, s_side>>>(edge);
    cudaEventRecord(ev_join, s_side);

    // ---- Layer 1 GEMM (single-stage full-K, fused dots) on main stream ----
    dim3 g1((NN + 127) / 128, 1, NH);
    hgemm1_kernel<<<g1, 256, GEMM1_SMEM>>>(
        type_emb, W, p_xsh, p_ssrc, p_sdst, att_src, att_dst);

    // ---- join: gather needs CSR + GEMM ----
    cudaStreamWaitEvent(0, ev_join, 0);

    dim3 gg1((NN * 32 + 255) / 256, 1, NH);
    gather1_kernel<<<gg1, 256>>>(bias);

    // ---- Layer 2: fp16 A GEMM, then gather ----
    dim3 g2((NN + 127) / 128, 1, 1);
    hgemm2_kernel<<<g2, 256>>>(
        p_xh, W_out, p_xs2h, p_ssrc2, p_sdst2, att_src_o, att_dst_o,
        NN, NH * FH);

    gather2_kernel<<<(NN * 32 + 255) / 256, 256>>>(out, bias_o);
}

// round 14
// speedup vs baseline: 3.6149x; 1.1047x over previous
#include <cuda_runtime.h>
#include <cuda_fp16.h>
#include <cstdint>
#include <math.h>

#define NN 50000      // nodes
#define EE 800000     // raw edges
#define ET 850000     // edges + self loops
#define FH 128        // F_IN == NHID
#define NH 4          // heads
#define NC 64         // classes
#define SLOPE 0.2f

// ---------------- static device scratch (no runtime alloc allowed) ----------
static __device__ __half g_xsh[(size_t)NN * NH * FH];  // layer1 feats, [n][h*128+c]
static __device__ __half g_xh[(size_t)NN * NH * FH];   // layer1 out / layer2 in, [n][512]
static __device__ __half g_xs2h[(size_t)NN * NC];      // layer2 feats, fp16
static __device__ float  g_ssrc[NN * NH];              // interleaved [n*4+h]
static __device__ float  g_sdst[NN * NH];              // interleaved [n*4+h]
static __device__ float  g_ssrc2[NN];
static __device__ float  g_sdst2[NN];
static __device__ int    g_deg[NN];
static __device__ int    g_row[NN + 1];
static __device__ int    g_fill[NN];
static __device__ int    g_csrc[ET];

__device__ __forceinline__ float lrelu(float x) { return x > 0.f ? x : SLOPE * x; }

__device__ __forceinline__ void mma_f16(float* d, const uint32_t* a, const uint32_t* b) {
    asm volatile(
        "mma.sync.aligned.m16n8k16.row.col.f32.f16.f16.f32 "
        "{%0,%1,%2,%3}, {%4,%5,%6,%7}, {%8,%9}, {%0,%1,%2,%3};"
        : "+f"(d[0]), "+f"(d[1]), "+f"(d[2]), "+f"(d[3])
        : "r"(a[0]), "r"(a[1]), "r"(a[2]), "r"(a[3]), "r"(b[0]), "r"(b[1]));
}
__device__ __forceinline__ void ldsm_x4(uint32_t& r0, uint32_t& r1, uint32_t& r2,
                                        uint32_t& r3, uint32_t a) {
    asm volatile("ldmatrix.sync.aligned.m8n8.x4.shared.b16 {%0,%1,%2,%3}, [%4];"
                 : "=r"(r0), "=r"(r1), "=r"(r2), "=r"(r3) : "r"(a));
}
__device__ __forceinline__ void ldsm_x4_t(uint32_t& r0, uint32_t& r1, uint32_t& r2,
                                          uint32_t& r3, uint32_t a) {
    asm volatile("ldmatrix.sync.aligned.m8n8.x4.trans.shared.b16 {%0,%1,%2,%3}, [%4];"
                 : "=r"(r0), "=r"(r1), "=r"(r2), "=r"(r3) : "r"(a));
}
__device__ __forceinline__ uint32_t h2u(__half2 h) {
    return *reinterpret_cast<uint32_t*>(&h);
}

// ---------------- CSR build --------------------------------------------------
__global__ void count_kernel(const int* __restrict__ edge) {
    int e = blockIdx.x * blockDim.x + threadIdx.x;
    if (e >= ET) return;
    int d = (e < EE) ? edge[EE + e] : (e - EE);
    atomicAdd(&g_deg[d], 1);
}

#define SCAN_T 1024
__global__ void scan_kernel() {
    __shared__ int sh[SCAN_T];
    const int tid = threadIdx.x;
    const int CH = (NN + SCAN_T - 1) / SCAN_T;
    const int base = tid * CH;
    int sum = 0;
    for (int k = 0; k < CH; k++) {
        int i = base + k;
        if (i < NN) sum += g_deg[i];
    }
    sh[tid] = sum;
    __syncthreads();
    for (int off = 1; off < SCAN_T; off <<= 1) {
        int v = (tid >= off) ? sh[tid - off] : 0;
        __syncthreads();
        sh[tid] += v;
        __syncthreads();
    }
    int run = (tid == 0) ? 0 : sh[tid - 1];
    for (int k = 0; k < CH; k++) {
        int i = base + k;
        if (i < NN) {
            g_row[i] = run;
            g_fill[i] = run;
            run += g_deg[i];
        }
    }
    if (tid == SCAN_T - 1) g_row[NN] = run;
}

__global__ void fill_kernel(const int* __restrict__ edge) {
    int e = blockIdx.x * blockDim.x + threadIdx.x;
    if (e >= ET) return;
    int s, d;
    if (e < EE) { s = edge[e]; d = edge[EE + e]; } else { s = d = e - EE; }
    int pos = atomicAdd(&g_fill[d], 1);
    g_csrc[pos] = s;
}

// ---------------- layer-1 GEMM: single-stage full-K, 512 threads ------------
// C[h] = A[h] (50000x128, fp32) @ B[h] (128x128, fp32); head = blockIdx.z.
// 16 warps (4m x 4n), warp tile 32x32, 2 CTAs/SM target (occ 50%).
// Epilogue: fp16 features at [row][h*128+col], logits at [row*NH+h].
__global__ void __launch_bounds__(512, 2)
hgemm1_kernel(const float* __restrict__ A, const float* __restrict__ B,
              __half* __restrict__ Ch,
              float* __restrict__ dsrc, float* __restrict__ ddst,
              const float* __restrict__ atts, const float* __restrict__ attd) {
    constexpr int BM = 128;
    constexpr int KK = 128;
    constexpr int BN = 128;
    constexpr int AST = 136;
    constexpr int BST = 136;
    constexpr int MT = 2;      // 16-row tiles (warp rows = 32)
    constexpr int NT = 4;      // 8-col tiles (warp cols = 32)

    extern __shared__ __align__(16) char dyn[];
    __half* As = reinterpret_cast<__half*>(dyn);            // 34816 B
    __half* Bs = reinterpret_cast<__half*>(dyn + 34816);    // 34816 B
    float* sds = reinterpret_cast<float*>(dyn + 69632);     // 4*128 floats
    float* sdd = reinterpret_cast<float*>(dyn + 71680);     // 4*128 floats

    const int tid = threadIdx.x;
    const int lane = tid & 31;
    const int wid = tid >> 5;
    const int wm = wid >> 2;       // 0..3
    const int wn = wid & 3;        // 0..3
    const int r = lane >> 2;
    const int c = lane & 3;
    const int h = blockIdx.z;
    const int rowBase = blockIdx.x * BM;

    A    += (size_t)h * NN * FH;
    B    += (size_t)h * FH * FH;
    Ch   += (size_t)h * FH;        // column offset within [n][512]
    atts += h * FH;
    attd += h * FH;

    // ---- load phase: 8+8 LDG.128 per thread (unroll 4 caps staging regs) ----
    #pragma unroll 4
    for (int t = 0; t < 8; t++) {
        int idx = tid + t * 512;
        int rr = idx >> 5;
        int c4 = (idx & 31) * 4;
        float4 v = make_float4(0.f, 0.f, 0.f, 0.f);
        if (rowBase + rr < NN)
            v = *reinterpret_cast<const float4*>(&A[(size_t)(rowBase + rr) * KK + c4]);
        uint2 u = make_uint2(h2u(__floats2half2_rn(v.x, v.y)),
                             h2u(__floats2half2_rn(v.z, v.w)));
        *reinterpret_cast<uint2*>(&As[rr * AST + c4]) = u;
    }
    #pragma unroll 4
    for (int t = 0; t < 8; t++) {
        int idx = tid + t * 512;
        int rr = idx >> 5;
        int c4 = (idx & 31) * 4;
        float4 v = *reinterpret_cast<const float4*>(&B[(size_t)rr * BN + c4]);
        uint2 u = make_uint2(h2u(__floats2half2_rn(v.x, v.y)),
                             h2u(__floats2half2_rn(v.z, v.w)));
        *reinterpret_cast<uint2*>(&Bs[rr * BST + c4]) = u;
    }
    __syncthreads();

    // ---- compute: 8 k-steps, no further syncs ----
    float acc[MT][NT][4] = {};
    const int m = lane >> 3;
    const int i = lane & 7;
    #pragma unroll
    for (int kk = 0; kk < KK; kk += 16) {
        uint32_t af[MT][4];
        #pragma unroll
        for (int mt = 0; mt < MT; mt++) {
            int row = wm * 32 + mt * 16 + (m & 1) * 8 + i;
            int col = kk + (m >> 1) * 8;
            uint32_t addr = (uint32_t)__cvta_generic_to_shared(&As[row * AST + col]);
            ldsm_x4(af[mt][0], af[mt][1], af[mt][2], af[mt][3], addr);
        }
        uint32_t bf[NT][2];
        #pragma unroll
        for (int j = 0; j < NT / 2; j++) {
            int krow = kk + (m & 1) * 8 + i;
            int col = wn * 32 + j * 16 + (m >> 1) * 8;
            uint32_t addr = (uint32_t)__cvta_generic_to_shared(&Bs[krow * BST + col]);
            ldsm_x4_t(bf[2 * j][0], bf[2 * j][1], bf[2 * j + 1][0], bf[2 * j + 1][1], addr);
        }
        #pragma unroll
        for (int mt = 0; mt < MT; mt++)
            #pragma unroll
            for (int nt = 0; nt < NT; nt++)
                mma_f16(acc[mt][nt], af[mt], bf[nt]);
    }

    // ---- epilogue: fp16 feature store (node-major layout) + fused dots ----
    float pds[MT][2] = {}, pdd[MT][2] = {};
    #pragma unroll
    for (int mt = 0; mt < MT; mt++) {
        int row0 = rowBase + wm * 32 + mt * 16 + r;
        #pragma unroll
        for (int nt = 0; nt < NT; nt++) {
            int col0 = wn * 32 + nt * 8 + 2 * c;
            float as0 = __ldg(&atts[col0]), as1 = __ldg(&atts[col0 + 1]);
            float ad0 = __ldg(&attd[col0]), ad1 = __ldg(&attd[col0 + 1]);
            float* d = acc[mt][nt];
            pds[mt][0] += d[0] * as0 + d[1] * as1;
            pds[mt][1] += d[2] * as0 + d[3] * as1;
            pdd[mt][0] += d[0] * ad0 + d[1] * ad1;
            pdd[mt][1] += d[2] * ad0 + d[3] * ad1;
            if (row0 < NN)
                *reinterpret_cast<__half2*>(&Ch[(size_t)row0 * (NH * FH) + col0]) =
                    __floats2half2_rn(d[0], d[1]);
            if (row0 + 8 < NN)
                *reinterpret_cast<__half2*>(&Ch[(size_t)(row0 + 8) * (NH * FH) + col0]) =
                    __floats2half2_rn(d[2], d[3]);
        }
    }
    #pragma unroll
    for (int mt = 0; mt < MT; mt++) {
        #pragma unroll
        for (int hh = 0; hh < 2; hh++) {
            pds[mt][hh] += __shfl_xor_sync(0xffffffffu, pds[mt][hh], 1);
            pds[mt][hh] += __shfl_xor_sync(0xffffffffu, pds[mt][hh], 2);
            pdd[mt][hh] += __shfl_xor_sync(0xffffffffu, pdd[mt][hh], 1);
            pdd[mt][hh] += __shfl_xor_sync(0xffffffffu, pdd[mt][hh], 2);
        }
    }
    if (c == 0) {
        #pragma unroll
        for (int mt = 0; mt < MT; mt++) {
            int rloc = wm * 32 + mt * 16 + r;
            sds[wn * 128 + rloc] = pds[mt][0];
            sdd[wn * 128 + rloc] = pdd[mt][0];
            sds[wn * 128 + rloc + 8] = pds[mt][1];
            sdd[wn * 128 + rloc + 8] = pdd[mt][1];
        }
    }
    __syncthreads();
    if (tid < BM) {
        int row = rowBase + tid;
        if (row < NN) {
            dsrc[(size_t)row * NH + h] =
                sds[tid] + sds[128 + tid] + sds[256 + tid] + sds[384 + tid];
            ddst[(size_t)row * NH + h] =
                sdd[tid] + sdd[128 + tid] + sdd[256 + tid] + sdd[384 + tid];
        }
    }
}

// ---------------- layer-2 GEMM: fp16 A, double-buffered, fused dots ---------
__global__ void __launch_bounds__(256)
hgemm2_kernel(const __half* __restrict__ A16, const float* __restrict__ B,
              __half* __restrict__ Ch,
              float* __restrict__ dsrc, float* __restrict__ ddst,
              const float* __restrict__ atts, const float* __restrict__ attd,
              int M, int K) {
    constexpr int BM = 128;
    constexpr int BK = 32;
    constexpr int BN = 64;
    constexpr int WN = 32;
    constexpr int AST = 40;
    constexpr int BST = BN + 8;
    constexpr int MT = 2;
    constexpr int NT = WN / 8;
    constexpr int A_LD = BM * BK / (8 * 256);   // 2
    constexpr int B_LD = BK * BN / (4 * 256);   // 2

    __shared__ __align__(16) __half As[2][BM * AST];
    __shared__ __align__(16) __half Bs[2][BK * BST];
    __shared__ float sds[2][BM], sdd[2][BM];

    const int tid = threadIdx.x;
    const int lane = tid & 31;
    const int wid = tid >> 5;
    const int wm = wid >> 1;
    const int wn = wid & 1;
    const int r = lane >> 2;
    const int c = lane & 3;
    const int rowBase = blockIdx.x * BM;

    float acc[MT][NT][4] = {};
    uint4  aS16[A_LD];
    float4 bS[B_LD];

    auto stage = [&](int k0) {
        #pragma unroll
        for (int t = 0; t < A_LD; t++) {
            int idx = tid + t * 256;
            int rr = idx >> 2;
            int c8 = (idx & 3) * 8;
            aS16[t] = (rowBase + rr < M)
                ? *reinterpret_cast<const uint4*>(&A16[(size_t)(rowBase + rr) * K + k0 + c8])
                : make_uint4(0, 0, 0, 0);
        }
        #pragma unroll
        for (int t = 0; t < B_LD; t++) {
            int idx = tid + t * 256;
            int rr = idx / (BN / 4);
            int c4 = (idx % (BN / 4)) * 4;
            bS[t] = *reinterpret_cast<const float4*>(&B[(size_t)(k0 + rr) * BN + c4]);
        }
    };
    auto commit = [&](int buf) {
        #pragma unroll
        for (int t = 0; t < A_LD; t++) {
            int idx = tid + t * 256;
            int rr = idx >> 2;
            int c8 = (idx & 3) * 8;
            *reinterpret_cast<uint4*>(&As[buf][rr * AST + c8]) = aS16[t];
        }
        #pragma unroll
        for (int t = 0; t < B_LD; t++) {
            int idx = tid + t * 256;
            int rr = idx / (BN / 4);
            int c4 = (idx % (BN / 4)) * 4;
            uint2 u = make_uint2(h2u(__floats2half2_rn(bS[t].x, bS[t].y)),
                                 h2u(__floats2half2_rn(bS[t].z, bS[t].w)));
            *reinterpret_cast<uint2*>(&Bs[buf][rr * BST + c4]) = u;
        }
    };
    auto compute = [&](int buf) {
        const int m = lane >> 3;
        const int i = lane & 7;
        #pragma unroll
        for (int ks = 0; ks < BK / 16; ks++) {
            const int kk = ks * 16;
            uint32_t af[MT][4];
            #pragma unroll
            for (int mt = 0; mt < MT; mt++) {
                int row = wm * 32 + mt * 16 + (m & 1) * 8 + i;
                int col = kk + (m >> 1) * 8;
                uint32_t addr = (uint32_t)__cvta_generic_to_shared(&As[buf][row * AST + col]);
                ldsm_x4(af[mt][0], af[mt][1], af[mt][2], af[mt][3], addr);
            }
            uint32_t bf[NT][2];
            #pragma unroll
            for (int j = 0; j < NT / 2; j++) {
                int krow = kk + (m & 1) * 8 + i;
                int col = wn * WN + j * 16 + (m >> 1) * 8;
                uint32_t addr = (uint32_t)__cvta_generic_to_shared(&Bs[buf][krow * BST + col]);
                ldsm_x4_t(bf[2 * j][0], bf[2 * j][1], bf[2 * j + 1][0], bf[2 * j + 1][1], addr);
            }
            #pragma unroll
            for (int mt = 0; mt < MT; mt++)
                #pragma unroll
                for (int nt = 0; nt < NT; nt++)
                    mma_f16(acc[mt][nt], af[mt], bf[nt]);
        }
    };

    stage(0);
    commit(0);
    __syncthreads();
    int buf = 0;
    for (int k0 = 0; k0 < K; k0 += BK) {
        if (k0 + BK < K) {
            stage(k0 + BK);
            compute(buf);
            commit(buf ^ 1);
            __syncthreads();
            buf ^= 1;
        } else {
            compute(buf);
        }
    }

    float pds[MT][2] = {}, pdd[MT][2] = {};
    #pragma unroll
    for (int mt = 0; mt < MT; mt++) {
        int row0 = rowBase + wm * 32 + mt * 16 + r;
        #pragma unroll
        for (int nt = 0; nt < NT; nt++) {
            int col0 = wn * WN + nt * 8 + 2 * c;
            float as0 = __ldg(&atts[col0]), as1 = __ldg(&atts[col0 + 1]);
            float ad0 = __ldg(&attd[col0]), ad1 = __ldg(&attd[col0 + 1]);
            float* d = acc[mt][nt];
            pds[mt][0] += d[0] * as0 + d[1] * as1;
            pds[mt][1] += d[2] * as0 + d[3] * as1;
            pdd[mt][0] += d[0] * ad0 + d[1] * ad1;
            pdd[mt][1] += d[2] * ad0 + d[3] * ad1;
            if (row0 < M)
                *reinterpret_cast<__half2*>(&Ch[(size_t)row0 * BN + col0]) =
                    __floats2half2_rn(d[0], d[1]);
            if (row0 + 8 < M)
                *reinterpret_cast<__half2*>(&Ch[(size_t)(row0 + 8) * BN + col0]) =
                    __floats2half2_rn(d[2], d[3]);
        }
    }
    #pragma unroll
    for (int mt = 0; mt < MT; mt++) {
        #pragma unroll
        for (int hh = 0; hh < 2; hh++) {
            pds[mt][hh] += __shfl_xor_sync(0xffffffffu, pds[mt][hh], 1);
            pds[mt][hh] += __shfl_xor_sync(0xffffffffu, pds[mt][hh], 2);
            pdd[mt][hh] += __shfl_xor_sync(0xffffffffu, pdd[mt][hh], 1);
            pdd[mt][hh] += __shfl_xor_sync(0xffffffffu, pdd[mt][hh], 2);
        }
    }
    if (c == 0) {
        #pragma unroll
        for (int mt = 0; mt < MT; mt++) {
            int rloc = wm * 32 + mt * 16 + r;
            sds[wn][rloc] = pds[mt][0];
            sdd[wn][rloc] = pdd[mt][0];
            sds[wn][rloc + 8] = pds[mt][1];
            sdd[wn][rloc + 8] = pdd[mt][1];
        }
    }
    __syncthreads();
    if (tid < BM) {
        int row = rowBase + tid;
        if (row < M) {
            dsrc[row] = sds[0][tid] + sds[1][tid];
            ddst[row] = sdd[0][tid] + sdd[1][tid];
        }
    }
}

// ---------------- layer 1 fused gather: all 4 heads per warp ----------------
// warp per node; per edge: 1 idx + 1 float4 logit + 4 uint2 feature loads.
__global__ void gather1_kernel(const float* __restrict__ bias) {
    long n = ((long)blockIdx.x * blockDim.x + threadIdx.x) >> 5;
    int lane = threadIdx.x & 31;
    if (n >= NN) return;

    const int beg = g_row[n];
    const int end = g_row[n + 1];
    const float4 sd = *reinterpret_cast<const float4*>(&g_sdst[(size_t)n * NH]);
    const float4* __restrict__ ss4 = reinterpret_cast<const float4*>(g_ssrc);
    const __half* __restrict__ xsh = g_xsh;

    float4 acc0 = make_float4(0.f, 0.f, 0.f, 0.f);
    float4 acc1 = acc0, acc2 = acc0, acc3 = acc0;
    float4 den = acc0;

    // prime 2-deep pipeline (self-loop guarantees beg < end)
    int s = g_csrc[beg];
    float4 ss = ss4[s];
    uint2 u0 = *reinterpret_cast<const uint2*>(&xsh[(size_t)s * (NH * FH) + 0 * FH + lane * 4]);
    uint2 u1 = *reinterpret_cast<const uint2*>(&xsh[(size_t)s * (NH * FH) + 1 * FH + lane * 4]);
    uint2 u2 = *reinterpret_cast<const uint2*>(&xsh[(size_t)s * (NH * FH) + 2 * FH + lane * 4]);
    uint2 u3 = *reinterpret_cast<const uint2*>(&xsh[(size_t)s * (NH * FH) + 3 * FH + lane * 4]);

    for (int j = beg; j < end; j++) {
        int sn = (j + 1 < end) ? g_csrc[j + 1] : s;
        float4 ssn = ss4[sn];
        uint2 n0 = *reinterpret_cast<const uint2*>(&xsh[(size_t)sn * (NH * FH) + 0 * FH + lane * 4]);
        uint2 n1 = *reinterpret_cast<const uint2*>(&xsh[(size_t)sn * (NH * FH) + 1 * FH + lane * 4]);
        uint2 n2 = *reinterpret_cast<const uint2*>(&xsh[(size_t)sn * (NH * FH) + 2 * FH + lane * 4]);
        uint2 n3 = *reinterpret_cast<const uint2*>(&xsh[(size_t)sn * (NH * FH) + 3 * FH + lane * 4]);

        float e0 = __expf(lrelu(ss.x + sd.x));
        float e1 = __expf(lrelu(ss.y + sd.y));
        float e2 = __expf(lrelu(ss.z + sd.z));
        float e3 = __expf(lrelu(ss.w + sd.w));
        den.x += e0; den.y += e1; den.z += e2; den.w += e3;

        float2 f;
        f = __half22float2(*reinterpret_cast<__half2*>(&u0.x)); acc0.x += e0 * f.x; acc0.y += e0 * f.y;
        f = __half22float2(*reinterpret_cast<__half2*>(&u0.y)); acc0.z += e0 * f.x; acc0.w += e0 * f.y;
        f = __half22float2(*reinterpret_cast<__half2*>(&u1.x)); acc1.x += e1 * f.x; acc1.y += e1 * f.y;
        f = __half22float2(*reinterpret_cast<__half2*>(&u1.y)); acc1.z += e1 * f.x; acc1.w += e1 * f.y;
        f = __half22float2(*reinterpret_cast<__half2*>(&u2.x)); acc2.x += e2 * f.x; acc2.y += e2 * f.y;
        f = __half22float2(*reinterpret_cast<__half2*>(&u2.y)); acc2.z += e2 * f.x; acc2.w += e2 * f.y;
        f = __half22float2(*reinterpret_cast<__half2*>(&u3.x)); acc3.x += e3 * f.x; acc3.y += e3 * f.y;
        f = __half22float2(*reinterpret_cast<__half2*>(&u3.y)); acc3.z += e3 * f.x; acc3.w += e3 * f.y;

        ss = ssn; u0 = n0; u1 = n1; u2 = n2; u3 = n3; s = sn;
    }

    __half* __restrict__ xo = &g_xh[(size_t)n * (NH * FH) + lane * 4];
    const float inv0 = 1.f / den.x, inv1 = 1.f / den.y;
    const float inv2 = 1.f / den.z, inv3 = 1.f / den.w;
    float4 b;
    uint2 o;
    b = *reinterpret_cast<const float4*>(&bias[0 * FH + lane * 4]);
    o.x = h2u(__floats2half2_rn(lrelu(acc0.x * inv0 + b.x), lrelu(acc0.y * inv0 + b.y)));
    o.y = h2u(__floats2half2_rn(lrelu(acc0.z * inv0 + b.z), lrelu(acc0.w * inv0 + b.w)));
    *reinterpret_cast<uint2*>(&xo[0 * FH]) = o;
    b = *reinterpret_cast<const float4*>(&bias[1 * FH + lane * 4]);
    o.x = h2u(__floats2half2_rn(lrelu(acc1.x * inv1 + b.x), lrelu(acc1.y * inv1 + b.y)));
    o.y = h2u(__floats2half2_rn(lrelu(acc1.z * inv1 + b.z), lrelu(acc1.w * inv1 + b.w)));
    *reinterpret_cast<uint2*>(&xo[1 * FH]) = o;
    b = *reinterpret_cast<const float4*>(&bias[2 * FH + lane * 4]);
    o.x = h2u(__floats2half2_rn(lrelu(acc2.x * inv2 + b.x), lrelu(acc2.y * inv2 + b.y)));
    o.y = h2u(__floats2half2_rn(lrelu(acc2.z * inv2 + b.z), lrelu(acc2.w * inv2 + b.w)));
    *reinterpret_cast<uint2*>(&xo[2 * FH]) = o;
    b = *reinterpret_cast<const float4*>(&bias[3 * FH + lane * 4]);
    o.x = h2u(__floats2half2_rn(lrelu(acc3.x * inv3 + b.x), lrelu(acc3.y * inv3 + b.y)));
    o.y = h2u(__floats2half2_rn(lrelu(acc3.z * inv3 + b.z), lrelu(acc3.w * inv3 + b.w)));
    *reinterpret_cast<uint2*>(&xo[3 * FH]) = o;
}

// ---------------- layer 2 fused gather: softmax-agg + bias + lrelu + tanh ---
__global__ void gather2_kernel(float* __restrict__ out, const float* __restrict__ bias_out) {
    long n = ((long)blockIdx.x * blockDim.x + threadIdx.x) >> 5;
    int lane = threadIdx.x & 31;
    if (n >= NN) return;

    const int beg = g_row[n];
    const int end = g_row[n + 1];
    const float sd = g_sdst2[n];

    float2 acc = make_float2(0.f, 0.f);
    float den = 0.f;

    int s = g_csrc[beg];
    float ss = g_ssrc2[s];
    __half2 hv = *reinterpret_cast<const __half2*>(&g_xs2h[(size_t)s * NC + lane * 2]);

    for (int j = beg; j < end; j++) {
        int sn = (j + 1 < end) ? g_csrc[j + 1] : s;
        float ssn = g_ssrc2[sn];
        __half2 hvn = *reinterpret_cast<const __half2*>(&g_xs2h[(size_t)sn * NC + lane * 2]);
        float ex = __expf(lrelu(ss + sd));
        float2 v = __half22float2(hv);
        den += ex;
        acc.x += ex * v.x; acc.y += ex * v.y;
        ss = ssn; hv = hvn;
    }
    const float inv = 1.f / den;
    const float2 b = *reinterpret_cast<const float2*>(&bias_out[lane * 2]);
    float2 o;
    o.x = tanhf(lrelu(acc.x * inv + b.x));
    o.y = tanhf(lrelu(acc.y * inv + b.y));
    *reinterpret_cast<float2*>(&out[(size_t)n * NC + lane * 2]) = o;
}

// ---------------- launch ----------------------------------------------------
extern "C" void kernel_launch(void* const* d_in, const int* in_sizes, int n_in,
                              void* d_out, int out_size) {
    const float* type_emb  = (const float*)d_in[0];  // [4,50000,128]
    const int*   edge      = (const int*)d_in[1];    // [2,800000]
    const float* W         = (const float*)d_in[2];  // [4,128,128]
    const float* att_src   = (const float*)d_in[3];  // [4,128]
    const float* att_dst   = (const float*)d_in[4];  // [4,128]
    const float* bias      = (const float*)d_in[5];  // [4,128]
    const float* W_out     = (const float*)d_in[6];  // [512,64]
    const float* att_src_o = (const float*)d_in[7];  // [64]
    const float* att_dst_o = (const float*)d_in[8];  // [64]
    const float* bias_o    = (const float*)d_in[9];  // [64]
    float* out = (float*)d_out;                      // [50000,64]
    (void)in_sizes; (void)n_in; (void)out_size;

    __half *p_xsh, *p_xh, *p_xs2h;
    float *p_ssrc, *p_sdst, *p_ssrc2, *p_sdst2;
    int *p_deg;
    cudaGetSymbolAddress((void**)&p_xsh, g_xsh);
    cudaGetSymbolAddress((void**)&p_xh, g_xh);
    cudaGetSymbolAddress((void**)&p_xs2h, g_xs2h);
    cudaGetSymbolAddress((void**)&p_ssrc, g_ssrc);
    cudaGetSymbolAddress((void**)&p_sdst, g_sdst);
    cudaGetSymbolAddress((void**)&p_ssrc2, g_ssrc2);
    cudaGetSymbolAddress((void**)&p_sdst2, g_sdst2);
    cudaGetSymbolAddress((void**)&p_deg, g_deg);

    constexpr int GEMM1_SMEM = 73728;   // 2*34816 + 2*2048

    // one-time host objects (created on the uncaptured correctness call)
    static cudaStream_t s_side = nullptr;
    static cudaEvent_t ev_fork = nullptr, ev_join = nullptr;
    if (s_side == nullptr) {
        cudaStreamCreateWithFlags(&s_side, cudaStreamNonBlocking);
        cudaEventCreateWithFlags(&ev_fork, cudaEventDisableTiming);
        cudaEventCreateWithFlags(&ev_join, cudaEventDisableTiming);
        cudaFuncSetAttribute(hgemm1_kernel,
                             cudaFuncAttributeMaxDynamicSharedMemorySize, GEMM1_SMEM);
    }

    // ---- fork: CSR build on side stream, overlapped with layer-1 GEMM ----
    cudaEventRecord(ev_fork, 0);
    cudaStreamWaitEvent(s_side, ev_fork, 0);
    cudaMemsetAsync(p_deg, 0, NN * sizeof(int), s_side);
    count_kernel<<<(ET + 255) / 256, 256, 0, s_side>>>(edge);
    scan_kernel<<<1, SCAN_T, 0, s_side>>>();
    fill_kernel<<<(ET + 255) / 256, 256, 0, s_side>>>(edge);
    cudaEventRecord(ev_join, s_side);

    // ---- Layer 1 GEMM (single-stage full-K, 512 thr, fused dots) ----
    dim3 g1((NN + 127) / 128, 1, NH);
    hgemm1_kernel<<<g1, 512, GEMM1_SMEM>>>(
        type_emb, W, p_xsh, p_ssrc, p_sdst, att_src, att_dst);

    // ---- join: gather needs CSR + GEMM ----
    cudaStreamWaitEvent(0, ev_join, 0);

    gather1_kernel<<<(int)(((long)NN * 32 + 255) / 256), 256>>>(bias);

    // ---- Layer 2: fp16 A GEMM, then gather ----
    dim3 g2((NN + 127) / 128, 1, 1);
    hgemm2_kernel<<<g2, 256>>>(
        p_xh, W_out, p_xs2h, p_ssrc2, p_sdst2, att_src_o, att_dst_o,
        NN, NH * FH);

    gather2_kernel<<<(NN * 32 + 255) / 256, 256>>>(out, bias_o);
}